// round 1
// baseline (speedup 1.0000x reference)
#include <cuda_runtime.h>
#include <math.h>

#define Ecnt 40000
#define Bsz 32
#define Hd 128
#define NRELc 400
#define RSIZEc 200
#define TAU1 10.0f

// ---------------- scratch (static device memory; no allocs) ----------------
__device__ float g_states[5][Ecnt * Bsz];   // raw (unnormalized) states, layout [e*32+b]
__device__ float g_inp[Ecnt * Bsz];         // att-combined input to propagate
__device__ float g_rnn[4][Bsz * Hd];        // LSTM hidden per step
__device__ float g_h[Bsz * Hd];
__device__ float g_c[Bsz * Hd];
__device__ float g_WihT[Hd * 4 * Hd];       // [d][k] transposed for coalesced GEMV
__device__ float g_WhhT[Hd * 4 * Hd];
__device__ float g_linWT[Hd * NRELc];       // [d][r]
__device__ float g_wT[3][NRELc * Bsz];      // softmaxed relation weights, [t][r*32+b]
__device__ float g_attn[4 * Bsz];           // att premultiplied by norm, [tp*32+b]
__device__ float g_sums[Bsz];
__device__ float g_norm[5 * Bsz];           // 1/max(sum,1e-7) per state

__device__ __forceinline__ float sigf(float x) { return 1.0f / (1.0f + expf(-x)); }

__device__ __forceinline__ void red_add_v4(float4* p, float4 v) {
    asm volatile("red.global.add.v4.f32 [%0], {%1, %2, %3, %4};"
                 :: "l"(p), "f"(v.x), "f"(v.y), "f"(v.z), "f"(v.w)
                 : "memory");
}

// ---------------- init ----------------
__global__ void k_init() {
    int i = blockIdx.x * blockDim.x + threadIdx.x;
    int stride = gridDim.x * blockDim.x;
    for (int j = i; j < Ecnt * Bsz; j += stride) g_states[0][j] = 0.0f;
    for (int j = i; j < Bsz * Hd; j += stride) { g_h[j] = 0.0f; g_c[j] = 0.0f; }
    if (i < 5 * Bsz) g_norm[i] = 1.0f;
    if (i < Bsz) g_sums[i] = 0.0f;
}

__global__ void k_onehot(const int* __restrict__ input_x) {
    int b = threadIdx.x;
    if (b < Bsz) g_states[0][input_x[b] * Bsz + b] = 1.0f;
}

// ---------------- weight transposes ----------------
__global__ void k_transpose(const float* __restrict__ W_ih,
                            const float* __restrict__ W_hh,
                            const float* __restrict__ lin_W) {
    int i = blockIdx.x * blockDim.x + threadIdx.x;
    int stride = gridDim.x * blockDim.x;
    for (int j = i; j < 4 * Hd * Hd; j += stride) {
        int k = j / Hd, d = j % Hd;
        g_WihT[d * (4 * Hd) + k] = W_ih[j];
        g_WhhT[d * (4 * Hd) + k] = W_hh[j];
    }
    for (int j = i; j < NRELc * Hd; j += stride) {
        int r = j / Hd, d = j % Hd;
        g_linWT[d * NRELc + r] = lin_W[j];
    }
}

// ---------------- LSTM step (32 blocks = batch, 512 threads = gates) -------
__global__ void k_lstm(const float* __restrict__ emb_W, const int* __restrict__ input_r,
                       const float* __restrict__ b_ih, const float* __restrict__ b_hh, int t) {
    __shared__ float xs[Hd];
    __shared__ float hs[Hd];
    __shared__ float gsh[4 * Hd];
    int b = blockIdx.x;
    int k = threadIdx.x;  // 0..511
    if (k < Hd) {
        int row = (t < 3) ? input_r[b] : NRELc;
        xs[k] = emb_W[row * Hd + k];
        hs[k] = g_h[b * Hd + k];
    }
    __syncthreads();
    float acc = b_ih[k] + b_hh[k];
#pragma unroll 4
    for (int d = 0; d < Hd; d++)
        acc += xs[d] * g_WihT[d * (4 * Hd) + k] + hs[d] * g_WhhT[d * (4 * Hd) + k];
    gsh[k] = acc;
    __syncthreads();
    if (k < Hd) {
        float ig = gsh[k], fg = gsh[Hd + k], gg = gsh[2 * Hd + k], og = gsh[3 * Hd + k];
        float c = sigf(fg) * g_c[b * Hd + k] + sigf(ig) * tanhf(gg);
        float h = sigf(og) * tanhf(c);
        g_c[b * Hd + k] = c;
        g_h[b * Hd + k] = h;
        g_rnn[t][b * Hd + k] = h;
    }
}

// ---------------- relation-weight softmax (96 blocks = t*32+b, 128 thr) ----
__global__ void k_wsoft(const float* __restrict__ lin_b) {
    int t = blockIdx.x / Bsz, b = blockIdx.x % Bsz;
    __shared__ float rs[Hd];
    __shared__ float lg[NRELc];
    __shared__ float red[128];
    int tid = threadIdx.x;
    if (tid < Hd) rs[tid] = g_rnn[t][b * Hd + tid];
    __syncthreads();
    float lmax = -1e30f;
    for (int r = tid; r < NRELc; r += 128) {
        float acc = lin_b[r];
        for (int d = 0; d < Hd; d++) acc += rs[d] * g_linWT[d * NRELc + r];
        acc *= TAU1;
        lg[r] = acc;
        lmax = fmaxf(lmax, acc);
    }
    red[tid] = lmax;
    __syncthreads();
    for (int s = 64; s > 0; s >>= 1) {
        if (tid < s) red[tid] = fmaxf(red[tid], red[tid + s]);
        __syncthreads();
    }
    float m = red[0];
    __syncthreads();
    float lsum = 0.0f;
    for (int r = tid; r < NRELc; r += 128) {
        float e = expf(lg[r] - m);
        lg[r] = e;
        lsum += e;
    }
    red[tid] = lsum;
    __syncthreads();
    for (int s = 64; s > 0; s >>= 1) {
        if (tid < s) red[tid] += red[tid + s];
        __syncthreads();
    }
    float inv = 1.0f / red[0];
    for (int r = tid; r < NRELc; r += 128) g_wT[t][r * Bsz + b] = lg[r] * inv;
}

// ---------------- attention (1 block, 128 threads) --------------------------
__global__ void k_att(int t) {
    __shared__ float lg[Bsz][4];
    int tid = threadIdx.x;
    int b = tid >> 2, tp = tid & 3;
    float v = 0.0f;
    if (tp <= t) {
        for (int d = 0; d < Hd; d++) v += g_rnn[t][b * Hd + d] * g_rnn[tp][b * Hd + d];
    }
    lg[b][tp] = v;
    __syncthreads();
    if (tid < Bsz) {
        int b2 = tid;
        float m = -1e30f;
        for (int j = 0; j <= t; j++) m = fmaxf(m, lg[b2][j]);
        float s = 0.0f, e[4];
        for (int j = 0; j <= t; j++) { e[j] = expf(lg[b2][j] - m); s += e[j]; }
        float inv = 1.0f / s;
        for (int j = 0; j <= t; j++)
            g_attn[j * Bsz + b2] = e[j] * inv * g_norm[j * Bsz + b2];
        for (int j = t + 1; j < 4; j++) g_attn[j * Bsz + b2] = 0.0f;
        g_sums[b2] = 0.0f;  // reset for this step's reduction
    }
}

// ---------------- combine states -> g_inp, zero next state ------------------
__global__ void k_inp(int t) {
    int tid = blockIdx.x * blockDim.x + threadIdx.x;
    int stride = gridDim.x * blockDim.x;
    int b = tid & 31;  // stride is multiple of 32 -> constant per thread
    float a0 = g_attn[0 * Bsz + b];
    float a1 = g_attn[1 * Bsz + b];
    float a2 = g_attn[2 * Bsz + b];
    for (int j = tid; j < Ecnt * Bsz; j += stride) {
        float v = a0 * g_states[0][j];
        if (t >= 1) v += a1 * g_states[1][j];
        if (t >= 2) v += a2 * g_states[2][j];
        g_inp[j] = v;
        g_states[t + 1][j] = 0.0f;
    }
}

// ---------------- propagate: 1M edges, 8 lanes/edge (float4 over batch) ----
__global__ void k_prop(const int* __restrict__ heads, const int* __restrict__ tails,
                       const int* __restrict__ rels, int t, int nE) {
    const float4* __restrict__ x4 = reinterpret_cast<const float4*>(g_inp);
    float4* s4 = reinterpret_cast<float4*>(g_states[t + 1]);
    const float4* __restrict__ w4 = reinterpret_cast<const float4*>(g_wT[t]);
    int lane = threadIdx.x & 31;
    int q = lane & 7;       // float4 index within the 32 batch lanes
    int sub = lane >> 3;    // which of 4 edges this 8-lane group handles
    int warpId = (blockIdx.x * blockDim.x + threadIdx.x) >> 5;
    int nWarp = (gridDim.x * blockDim.x) >> 5;
    for (int e = warpId * 4 + sub; e < nE; e += nWarp * 4) {
        int h = heads[e], tl = tails[e], r = rels[e];
        float4 xh = x4[h * 8 + q];
        float4 xt = x4[tl * 8 + q];
        float4 w1 = w4[r * 8 + q];
        float4 w2 = w4[(r + RSIZEc) * 8 + q];
        float4 m1 = make_float4(xh.x * w1.x, xh.y * w1.y, xh.z * w1.z, xh.w * w1.w);
        float4 m2 = make_float4(xt.x * w2.x, xt.y * w2.y, xt.z * w2.z, xt.w * w2.w);
        red_add_v4(&s4[tl * 8 + q], m1);
        red_add_v4(&s4[h * 8 + q], m2);
    }
}

// ---------------- per-batch sum of the new state ----------------------------
__global__ void k_reduce(int t) {
    __shared__ float sh[8][32];
    int lane = threadIdx.x & 31;
    int w = threadIdx.x >> 5;
    const float* __restrict__ s = g_states[t + 1];
    float acc = 0.0f;
    for (int j = blockIdx.x * blockDim.x + threadIdx.x; j < Ecnt * Bsz;
         j += gridDim.x * blockDim.x)
        acc += s[j];  // j & 31 == lane (strides are multiples of 32)
    sh[w][lane] = acc;
    __syncthreads();
    if (w == 0) {
        float a = 0.0f;
        for (int k = 0; k < 8; k++) a += sh[k][lane];
        atomicAdd(&g_sums[lane], a);
    }
}

__global__ void k_norm(int t) {
    int b = threadIdx.x;
    if (b < Bsz) g_norm[(t + 1) * Bsz + b] = 1.0f / fmaxf(g_sums[b], 1e-7f);
}

// ---------------- final combine + transpose to (B, E) -----------------------
__global__ void k_final(float* __restrict__ out) {
    int tid = blockIdx.x * blockDim.x + threadIdx.x;
    int stride = gridDim.x * blockDim.x;
    int b = tid & 31;
    float a0 = g_attn[0 * Bsz + b];
    float a1 = g_attn[1 * Bsz + b];
    float a2 = g_attn[2 * Bsz + b];
    float a3 = g_attn[3 * Bsz + b];
    for (int j = tid; j < Ecnt * Bsz; j += stride) {
        int e = j >> 5;
        float v = a0 * g_states[0][j] + a1 * g_states[1][j] +
                  a2 * g_states[2][j] + a3 * g_states[3][j];
        out[b * Ecnt + e] = v;
    }
}

// ---------------- launch ----------------------------------------------------
extern "C" void kernel_launch(void* const* d_in, const int* in_sizes, int n_in,
                              void* d_out, int out_size) {
    const int* input_x = (const int*)d_in[0];
    const int* input_r = (const int*)d_in[1];
    const int* heads   = (const int*)d_in[2];
    const int* tails   = (const int*)d_in[3];
    const int* rels    = (const int*)d_in[4];
    const float* emb_W = (const float*)d_in[5];
    const float* W_ih  = (const float*)d_in[6];
    const float* W_hh  = (const float*)d_in[7];
    const float* b_ih  = (const float*)d_in[8];
    const float* b_hh  = (const float*)d_in[9];
    const float* lin_W = (const float*)d_in[10];
    const float* lin_b = (const float*)d_in[11];
    int nE = in_sizes[2];
    float* out = (float*)d_out;

    k_init<<<256, 256>>>();
    k_onehot<<<1, 32>>>(input_x);
    k_transpose<<<256, 256>>>(W_ih, W_hh, lin_W);
    for (int t = 0; t < 4; t++)
        k_lstm<<<32, 512>>>(emb_W, input_r, b_ih, b_hh, t);
    k_wsoft<<<96, 128>>>(lin_b);
    for (int t = 0; t < 3; t++) {
        k_att<<<1, 128>>>(t);
        k_inp<<<1184, 256>>>(t);
        k_prop<<<1184, 256>>>(heads, tails, rels, t, nE);
        k_reduce<<<148, 256>>>(t);
        k_norm<<<1, 32>>>(t);
    }
    k_att<<<1, 128>>>(3);
    k_final<<<1184, 256>>>(out);
}

// round 2
// speedup vs baseline: 1.5738x; 1.5738x over previous
#include <cuda_runtime.h>
#include <math.h>

#define Ecnt 40000
#define Bsz 32
#define Hd 128
#define NRELc 400
#define RSIZEc 200
#define TAU1 10.0f

// ---------------- scratch (static device memory; no allocs) ----------------
__device__ float g_states[5][Ecnt * Bsz];   // raw (unnormalized) states, layout [e*32+b]
__device__ float g_inp[Ecnt * Bsz];         // att-combined input to propagate
__device__ unsigned char g_nz[Ecnt];        // per-entity nonzero flag for g_inp
__device__ float g_rnn[4][Bsz * Hd];        // LSTM hidden per step
__device__ float g_h[Bsz * Hd];
__device__ float g_c[Bsz * Hd];
__device__ float g_ihpre[2][Bsz * 4 * Hd];  // precomputed x@W_ih.T + b_ih + b_hh
__device__ float g_gates[Bsz * 4 * Hd];
__device__ float g_WihT[Hd * 4 * Hd];       // [d][k] transposed for coalesced GEMV
__device__ float g_WhhT[Hd * 4 * Hd];
__device__ float g_linWT[Hd * NRELc];       // [d][r]
__device__ float g_wT[3][NRELc * Bsz];      // softmaxed relation weights, [t][r*32+b]
__device__ float g_attn[4 * Bsz];           // att premultiplied by norm, [tp*32+b]
__device__ float g_sums[Bsz];
__device__ float g_norm[5 * Bsz];           // 1/max(sum,1e-7) per state

__device__ __forceinline__ float sigf(float x) { return 1.0f / (1.0f + expf(-x)); }

__device__ __forceinline__ void red_add_v4(float4* p, float4 v) {
    asm volatile("red.global.add.v4.f32 [%0], {%1, %2, %3, %4};"
                 :: "l"(p), "f"(v.x), "f"(v.y), "f"(v.z), "f"(v.w)
                 : "memory");
}

// ---------------- init ----------------
__global__ void k_init() {
    int i = blockIdx.x * blockDim.x + threadIdx.x;
    int stride = gridDim.x * blockDim.x;
    for (int j = i; j < Ecnt * Bsz; j += stride) g_states[0][j] = 0.0f;
    for (int j = i; j < Bsz * Hd; j += stride) { g_h[j] = 0.0f; g_c[j] = 0.0f; }
    if (i < 5 * Bsz) g_norm[i] = 1.0f;
    if (i < Bsz) g_sums[i] = 0.0f;
}

__global__ void k_onehot(const int* __restrict__ input_x) {
    int b = threadIdx.x;
    if (b < Bsz) g_states[0][input_x[b] * Bsz + b] = 1.0f;
}

// ---------------- weight transposes ----------------
__global__ void k_transpose(const float* __restrict__ W_ih,
                            const float* __restrict__ W_hh,
                            const float* __restrict__ lin_W) {
    int i = blockIdx.x * blockDim.x + threadIdx.x;
    int stride = gridDim.x * blockDim.x;
    for (int j = i; j < 4 * Hd * Hd; j += stride) {
        int k = j / Hd, d = j % Hd;
        g_WihT[d * (4 * Hd) + k] = W_ih[j];
        g_WhhT[d * (4 * Hd) + k] = W_hh[j];
    }
    for (int j = i; j < NRELc * Hd; j += stride) {
        int r = j / Hd, d = j % Hd;
        g_linWT[d * NRELc + r] = lin_W[j];
    }
}

// ---------------- precompute input-gate GEMV (only 2 unique x rows) --------
// grid 128 blocks x 256 thr: which = blk>>6, b = (blk&63)>>1, k = ((blk&1)<<8)+tid
__global__ void k_ih(const float* __restrict__ emb_W, const int* __restrict__ input_r,
                     const float* __restrict__ b_ih, const float* __restrict__ b_hh) {
    __shared__ float xs[Hd];
    int which = blockIdx.x >> 6;
    int rem = blockIdx.x & 63;
    int b = rem >> 1;
    int k = ((rem & 1) << 8) + threadIdx.x;
    if (threadIdx.x < Hd) {
        int row = which ? NRELc : input_r[b];
        xs[threadIdx.x] = emb_W[row * Hd + threadIdx.x];
    }
    __syncthreads();
    float acc = b_ih[k] + b_hh[k];
#pragma unroll 8
    for (int d = 0; d < Hd; d++) acc += xs[d] * g_WihT[d * (4 * Hd) + k];
    g_ihpre[which][b * (4 * Hd) + k] = acc;
}

// ---------------- per-step hidden GEMV (128 blocks x 128 thr) --------------
__global__ void k_hh(int t) {
    __shared__ float hs[Hd];
    int b = blockIdx.x >> 2;
    int k = ((blockIdx.x & 3) << 7) + threadIdx.x;
    hs[threadIdx.x] = g_h[b * Hd + threadIdx.x];
    __syncthreads();
    int which = (t < 3) ? 0 : 1;
    float acc = g_ihpre[which][b * (4 * Hd) + k];
#pragma unroll 8
    for (int d = 0; d < Hd; d++) acc += hs[d] * g_WhhT[d * (4 * Hd) + k];
    g_gates[b * (4 * Hd) + k] = acc;
}

// ---------------- LSTM cell elementwise (32 blocks x 128 thr) --------------
__global__ void k_cell(int t) {
    int b = blockIdx.x, k = threadIdx.x;
    const float* g = &g_gates[b * (4 * Hd)];
    float ig = g[k], fg = g[Hd + k], gg = g[2 * Hd + k], og = g[3 * Hd + k];
    float c = sigf(fg) * g_c[b * Hd + k] + sigf(ig) * tanhf(gg);
    float h = sigf(og) * tanhf(c);
    g_c[b * Hd + k] = c;
    g_h[b * Hd + k] = h;
    g_rnn[t][b * Hd + k] = h;
}

// ---------------- relation-weight softmax (96 blocks = t*32+b, 128 thr) ----
__global__ void k_wsoft(const float* __restrict__ lin_b) {
    int t = blockIdx.x / Bsz, b = blockIdx.x % Bsz;
    __shared__ float rs[Hd];
    __shared__ float lg[NRELc];
    __shared__ float red[128];
    int tid = threadIdx.x;
    if (tid < Hd) rs[tid] = g_rnn[t][b * Hd + tid];
    __syncthreads();
    float lmax = -1e30f;
    for (int r = tid; r < NRELc; r += 128) {
        float acc = lin_b[r];
        for (int d = 0; d < Hd; d++) acc += rs[d] * g_linWT[d * NRELc + r];
        acc *= TAU1;
        lg[r] = acc;
        lmax = fmaxf(lmax, acc);
    }
    red[tid] = lmax;
    __syncthreads();
    for (int s = 64; s > 0; s >>= 1) {
        if (tid < s) red[tid] = fmaxf(red[tid], red[tid + s]);
        __syncthreads();
    }
    float m = red[0];
    __syncthreads();
    float lsum = 0.0f;
    for (int r = tid; r < NRELc; r += 128) {
        float e = expf(lg[r] - m);
        lg[r] = e;
        lsum += e;
    }
    red[tid] = lsum;
    __syncthreads();
    for (int s = 64; s > 0; s >>= 1) {
        if (tid < s) red[tid] += red[tid + s];
        __syncthreads();
    }
    float inv = 1.0f / red[0];
    for (int r = tid; r < NRELc; r += 128) g_wT[t][r * Bsz + b] = lg[r] * inv;
}

// ---------------- attention (1 block, 128 threads) --------------------------
__global__ void k_att(int t) {
    __shared__ float lg[Bsz][4];
    int tid = threadIdx.x;
    int b = tid >> 2, tp = tid & 3;
    float v = 0.0f;
    if (tp <= t) {
        for (int d = 0; d < Hd; d++) v += g_rnn[t][b * Hd + d] * g_rnn[tp][b * Hd + d];
    }
    lg[b][tp] = v;
    __syncthreads();
    if (tid < Bsz) {
        int b2 = tid;
        float m = -1e30f;
        for (int j = 0; j <= t; j++) m = fmaxf(m, lg[b2][j]);
        float s = 0.0f, e[4];
        for (int j = 0; j <= t; j++) { e[j] = expf(lg[b2][j] - m); s += e[j]; }
        float inv = 1.0f / s;
        for (int j = 0; j <= t; j++)
            g_attn[j * Bsz + b2] = e[j] * inv * g_norm[j * Bsz + b2];
        for (int j = t + 1; j < 4; j++) g_attn[j * Bsz + b2] = 0.0f;
        g_sums[b2] = 0.0f;  // reset for this step's reduction
    }
}

// ---------------- combine states -> g_inp, nz flags, zero next state -------
__global__ void k_inp(int t) {
    int tid = blockIdx.x * blockDim.x + threadIdx.x;
    int stride = gridDim.x * blockDim.x;
    int lane = threadIdx.x & 31;
    float a0 = g_attn[0 * Bsz + lane];
    float a1 = g_attn[1 * Bsz + lane];
    float a2 = g_attn[2 * Bsz + lane];
    for (int j = tid; j < Ecnt * Bsz; j += stride) {
        float v = a0 * g_states[0][j];
        if (t >= 1) v += a1 * g_states[1][j];
        if (t >= 2) v += a2 * g_states[2][j];
        g_inp[j] = v;
        g_states[t + 1][j] = 0.0f;
        unsigned m = __ballot_sync(0xffffffffu, v != 0.0f);
        if (lane == 0) g_nz[j >> 5] = (m != 0u) ? 1 : 0;
    }
}

// ---------------- propagate: sparse-aware, fused batch sums ----------------
__global__ void k_prop(const int* __restrict__ heads, const int* __restrict__ tails,
                       const int* __restrict__ rels, int t, int nE) {
    const float4* __restrict__ x4 = reinterpret_cast<const float4*>(g_inp);
    float4* s4 = reinterpret_cast<float4*>(g_states[t + 1]);
    const float4* __restrict__ w4 = reinterpret_cast<const float4*>(g_wT[t]);
    int lane = threadIdx.x & 31;
    int q = lane & 7;       // float4 index within 32 batch lanes
    int sub = lane >> 3;    // which of 4 edges this 8-lane group handles
    int warpId = (blockIdx.x * blockDim.x + threadIdx.x) >> 5;
    int nWarp = (gridDim.x * blockDim.x) >> 5;
    float4 acc = make_float4(0.0f, 0.0f, 0.0f, 0.0f);
    for (int e = warpId * 4 + sub; e < nE; e += nWarp * 4) {
        int h = heads[e], tl = tails[e];
        bool fh = g_nz[h] != 0, ft = g_nz[tl] != 0;
        if (fh | ft) {
            int r = rels[e];
            if (fh) {
                float4 xh = x4[h * 8 + q];
                if (xh.x != 0.0f || xh.y != 0.0f || xh.z != 0.0f || xh.w != 0.0f) {
                    float4 w1 = w4[r * 8 + q];
                    float4 m1 = make_float4(xh.x * w1.x, xh.y * w1.y,
                                            xh.z * w1.z, xh.w * w1.w);
                    red_add_v4(&s4[tl * 8 + q], m1);
                    acc.x += m1.x; acc.y += m1.y; acc.z += m1.z; acc.w += m1.w;
                }
            }
            if (ft) {
                float4 xt = x4[tl * 8 + q];
                if (xt.x != 0.0f || xt.y != 0.0f || xt.z != 0.0f || xt.w != 0.0f) {
                    float4 w2 = w4[(r + RSIZEc) * 8 + q];
                    float4 m2 = make_float4(xt.x * w2.x, xt.y * w2.y,
                                            xt.z * w2.z, xt.w * w2.w);
                    red_add_v4(&s4[h * 8 + q], m2);
                    acc.x += m2.x; acc.y += m2.y; acc.z += m2.z; acc.w += m2.w;
                }
            }
        }
    }
    // reduce acc across the 4 lanes sharing each q (xor 8, 16)
    acc.x += __shfl_xor_sync(0xffffffffu, acc.x, 8);
    acc.y += __shfl_xor_sync(0xffffffffu, acc.y, 8);
    acc.z += __shfl_xor_sync(0xffffffffu, acc.z, 8);
    acc.w += __shfl_xor_sync(0xffffffffu, acc.w, 8);
    acc.x += __shfl_xor_sync(0xffffffffu, acc.x, 16);
    acc.y += __shfl_xor_sync(0xffffffffu, acc.y, 16);
    acc.z += __shfl_xor_sync(0xffffffffu, acc.z, 16);
    acc.w += __shfl_xor_sync(0xffffffffu, acc.w, 16);
    __shared__ float sblk[Bsz];
    if (threadIdx.x < Bsz) sblk[threadIdx.x] = 0.0f;
    __syncthreads();
    if (lane < 8) {
        atomicAdd(&sblk[q * 4 + 0], acc.x);
        atomicAdd(&sblk[q * 4 + 1], acc.y);
        atomicAdd(&sblk[q * 4 + 2], acc.z);
        atomicAdd(&sblk[q * 4 + 3], acc.w);
    }
    __syncthreads();
    if (threadIdx.x < Bsz) atomicAdd(&g_sums[threadIdx.x], sblk[threadIdx.x]);
}

__global__ void k_norm(int t) {
    int b = threadIdx.x;
    if (b < Bsz) g_norm[(t + 1) * Bsz + b] = 1.0f / fmaxf(g_sums[b], 1e-7f);
}

// ---------------- final combine + transpose to (B, E) -----------------------
__global__ void k_final(float* __restrict__ out) {
    int tid = blockIdx.x * blockDim.x + threadIdx.x;
    int stride = gridDim.x * blockDim.x;
    int b = tid & 31;
    float a0 = g_attn[0 * Bsz + b];
    float a1 = g_attn[1 * Bsz + b];
    float a2 = g_attn[2 * Bsz + b];
    float a3 = g_attn[3 * Bsz + b];
    for (int j = tid; j < Ecnt * Bsz; j += stride) {
        int e = j >> 5;
        float v = a0 * g_states[0][j] + a1 * g_states[1][j] +
                  a2 * g_states[2][j] + a3 * g_states[3][j];
        out[b * Ecnt + e] = v;
    }
}

// ---------------- launch ----------------------------------------------------
extern "C" void kernel_launch(void* const* d_in, const int* in_sizes, int n_in,
                              void* d_out, int out_size) {
    const int* input_x = (const int*)d_in[0];
    const int* input_r = (const int*)d_in[1];
    const int* heads   = (const int*)d_in[2];
    const int* tails   = (const int*)d_in[3];
    const int* rels    = (const int*)d_in[4];
    const float* emb_W = (const float*)d_in[5];
    const float* W_ih  = (const float*)d_in[6];
    const float* W_hh  = (const float*)d_in[7];
    const float* b_ih  = (const float*)d_in[8];
    const float* b_hh  = (const float*)d_in[9];
    const float* lin_W = (const float*)d_in[10];
    const float* lin_b = (const float*)d_in[11];
    int nE = in_sizes[2];
    float* out = (float*)d_out;

    k_init<<<256, 256>>>();
    k_onehot<<<1, 32>>>(input_x);
    k_transpose<<<256, 256>>>(W_ih, W_hh, lin_W);
    k_ih<<<128, 256>>>(emb_W, input_r, b_ih, b_hh);
    for (int t = 0; t < 4; t++) {
        k_hh<<<128, 128>>>(t);
        k_cell<<<32, 128>>>(t);
    }
    k_wsoft<<<96, 128>>>(lin_b);
    for (int t = 0; t < 3; t++) {
        k_att<<<1, 128>>>(t);
        k_inp<<<1184, 256>>>(t);
        k_prop<<<1184, 256>>>(heads, tails, rels, t, nE);
        k_norm<<<1, 32>>>(t);
    }
    k_att<<<1, 128>>>(3);
    k_final<<<1184, 256>>>(out);
}

// round 3
// speedup vs baseline: 1.6980x; 1.0789x over previous
#include <cuda_runtime.h>
#include <math.h>

#define Ecnt 40000
#define Bsz 32
#define Hd 128
#define NRELc 400
#define RSIZEc 200
#define TAU1 10.0f

// ---------------- scratch (static device memory; no allocs) ----------------
__device__ float g_states[5][Ecnt * Bsz];   // raw (unnormalized) states, layout [e*32+b]
__device__ float g_inp[Ecnt * Bsz];         // att-combined input to propagate
__device__ unsigned char g_nz[Ecnt];        // per-entity nonzero flag for g_inp
__device__ float g_rnn[4][Bsz * Hd];        // LSTM hidden per step
__device__ float g_ihpre[2][Bsz * 4 * Hd];  // precomputed x@W_ih.T + b_ih + b_hh
__device__ float g_WhhT[Hd * 4 * Hd];       // [d][k]
__device__ float g_linWT[Hd * NRELc];       // [d][r]
__device__ float g_wT[3][NRELc * Bsz];      // softmaxed relation weights, [t][r*32+b]
__device__ float g_attn[4 * Bsz];           // att premultiplied by norm, [tp*32+b]
__device__ float g_sums[Bsz];
__device__ float g_norm[5 * Bsz];           // 1/max(sum,1e-7) per state

__device__ __forceinline__ float sigf(float x) { return 1.0f / (1.0f + expf(-x)); }

__device__ __forceinline__ void red_add_v4(float4* p, float4 v) {
    asm volatile("red.global.add.v4.f32 [%0], {%1, %2, %3, %4};"
                 :: "l"(p), "f"(v.x), "f"(v.y), "f"(v.z), "f"(v.w)
                 : "memory");
}

// ---------------- init ----------------
__global__ void k_init() {
    int i = blockIdx.x * blockDim.x + threadIdx.x;
    int stride = gridDim.x * blockDim.x;
    for (int j = i; j < Ecnt * Bsz; j += stride) g_states[0][j] = 0.0f;
    if (i < 5 * Bsz) g_norm[i] = 1.0f;
    if (i < Bsz) g_sums[i] = 0.0f;
}

__global__ void k_onehot(const int* __restrict__ input_x) {
    int b = threadIdx.x;
    if (b < Bsz) g_states[0][input_x[b] * Bsz + b] = 1.0f;
}

// ---------------- small transposes (W_hh, lin_W only) ----------------
__global__ void k_transpose(const float* __restrict__ W_hh,
                            const float* __restrict__ lin_W) {
    int i = blockIdx.x * blockDim.x + threadIdx.x;
    int stride = gridDim.x * blockDim.x;
    for (int j = i; j < 4 * Hd * Hd; j += stride) {
        int k = j / Hd, d = j % Hd;
        g_WhhT[d * (4 * Hd) + k] = W_hh[j];
    }
    for (int j = i; j < NRELc * Hd; j += stride) {
        int r = j / Hd, d = j % Hd;
        g_linWT[d * NRELc + r] = lin_W[j];
    }
}

// ---------------- input-gate GEMV: warp per output (2*32*512 outputs) ------
__global__ void k_ih(const float* __restrict__ emb_W, const int* __restrict__ input_r,
                     const float* __restrict__ W_ih,
                     const float* __restrict__ b_ih, const float* __restrict__ b_hh) {
    int wid = (blockIdx.x * blockDim.x + threadIdx.x) >> 5;
    int lane = threadIdx.x & 31;
    if (wid >= 2 * Bsz * 4 * Hd / 1) return;  // 32768 warps exactly
    int which = wid >> 14;            // 16384 warps per which
    int b = (wid >> 9) & 31;
    int k = wid & 511;
    int row = which ? NRELc : input_r[b];
    const float* __restrict__ xr = emb_W + row * Hd;
    const float* __restrict__ wr = W_ih + k * Hd;
    float acc = 0.0f;
#pragma unroll
    for (int i = 0; i < 4; i++) {
        int d = lane + 32 * i;
        acc += xr[d] * wr[d];
    }
#pragma unroll
    for (int s = 16; s > 0; s >>= 1) acc += __shfl_xor_sync(0xffffffffu, acc, s);
    if (lane == 0) g_ihpre[which][b * (4 * Hd) + k] = acc + b_ih[k] + b_hh[k];
}

// ---------------- all 4 LSTM steps in one kernel (32 blocks x 512 thr) -----
__global__ void k_lstm4() {
    __shared__ float hs[Hd];
    __shared__ float cs[Hd];
    __shared__ float gsh[4 * Hd];
    int b = blockIdx.x, k = threadIdx.x;
    float pre0 = g_ihpre[0][b * (4 * Hd) + k];
    float pre1 = g_ihpre[1][b * (4 * Hd) + k];
    if (k < Hd) { hs[k] = 0.0f; cs[k] = 0.0f; }
    __syncthreads();
#pragma unroll
    for (int t = 0; t < 4; t++) {
        float acc = (t < 3) ? pre0 : pre1;
#pragma unroll 8
        for (int d = 0; d < Hd; d++) acc += hs[d] * g_WhhT[d * (4 * Hd) + k];
        gsh[k] = acc;
        __syncthreads();
        if (k < Hd) {
            float ig = gsh[k], fg = gsh[Hd + k], gg = gsh[2 * Hd + k], og = gsh[3 * Hd + k];
            float c = sigf(fg) * cs[k] + sigf(ig) * tanhf(gg);
            float h = sigf(og) * tanhf(c);
            cs[k] = c;
            hs[k] = h;
            g_rnn[t][b * Hd + k] = h;
        }
        __syncthreads();
    }
}

// ---------------- relation-weight softmax (96 blocks = t*32+b, 128 thr) ----
__global__ void k_wsoft(const float* __restrict__ lin_b) {
    int t = blockIdx.x / Bsz, b = blockIdx.x % Bsz;
    __shared__ float rs[Hd];
    __shared__ float lg[NRELc];
    __shared__ float red[128];
    int tid = threadIdx.x;
    if (tid < Hd) rs[tid] = g_rnn[t][b * Hd + tid];
    __syncthreads();
    float lmax = -1e30f;
    for (int r = tid; r < NRELc; r += 128) {
        float acc = lin_b[r];
        for (int d = 0; d < Hd; d++) acc += rs[d] * g_linWT[d * NRELc + r];
        acc *= TAU1;
        lg[r] = acc;
        lmax = fmaxf(lmax, acc);
    }
    red[tid] = lmax;
    __syncthreads();
    for (int s = 64; s > 0; s >>= 1) {
        if (tid < s) red[tid] = fmaxf(red[tid], red[tid + s]);
        __syncthreads();
    }
    float m = red[0];
    __syncthreads();
    float lsum = 0.0f;
    for (int r = tid; r < NRELc; r += 128) {
        float e = expf(lg[r] - m);
        lg[r] = e;
        lsum += e;
    }
    red[tid] = lsum;
    __syncthreads();
    for (int s = 64; s > 0; s >>= 1) {
        if (tid < s) red[tid] += red[tid + s];
        __syncthreads();
    }
    float inv = 1.0f / red[0];
    for (int r = tid; r < NRELc; r += 128) g_wT[t][r * Bsz + b] = lg[r] * inv;
}

// ---------------- attention (1 block, 128 threads) --------------------------
__global__ void k_att(int t) {
    __shared__ float lg[Bsz][4];
    int tid = threadIdx.x;
    int b = tid >> 2, tp = tid & 3;
    float v = 0.0f;
    if (tp <= t) {
        for (int d = 0; d < Hd; d++) v += g_rnn[t][b * Hd + d] * g_rnn[tp][b * Hd + d];
    }
    lg[b][tp] = v;
    __syncthreads();
    if (tid < Bsz) {
        int b2 = tid;
        float m = -1e30f;
        for (int j = 0; j <= t; j++) m = fmaxf(m, lg[b2][j]);
        float s = 0.0f, e[4];
        for (int j = 0; j <= t; j++) { e[j] = expf(lg[b2][j] - m); s += e[j]; }
        float inv = 1.0f / s;
        for (int j = 0; j <= t; j++)
            g_attn[j * Bsz + b2] = e[j] * inv * g_norm[j * Bsz + b2];
        for (int j = t + 1; j < 4; j++) g_attn[j * Bsz + b2] = 0.0f;
        g_sums[b2] = 0.0f;  // reset for this step's reduction
    }
}

// ---------------- combine states -> g_inp, nz flags, zero next state -------
__global__ void k_inp(int t) {
    int tid = blockIdx.x * blockDim.x + threadIdx.x;
    int stride = gridDim.x * blockDim.x;
    int lane = threadIdx.x & 31;
    float a0 = g_attn[0 * Bsz + lane];
    float a1 = g_attn[1 * Bsz + lane];
    float a2 = g_attn[2 * Bsz + lane];
    for (int j = tid; j < Ecnt * Bsz; j += stride) {
        float v = a0 * g_states[0][j];
        if (t >= 1) v += a1 * g_states[1][j];
        if (t >= 2) v += a2 * g_states[2][j];
        g_inp[j] = v;
        g_states[t + 1][j] = 0.0f;
        unsigned m = __ballot_sync(0xffffffffu, v != 0.0f);
        if (lane == 0) g_nz[j >> 5] = (m != 0u) ? 1 : 0;
    }
}

// ---------------- propagate: sparse-aware, fused batch sums ----------------
__global__ void k_prop(const int* __restrict__ heads, const int* __restrict__ tails,
                       const int* __restrict__ rels, int t, int nE) {
    const float4* __restrict__ x4 = reinterpret_cast<const float4*>(g_inp);
    float4* s4 = reinterpret_cast<float4*>(g_states[t + 1]);
    const float4* __restrict__ w4 = reinterpret_cast<const float4*>(g_wT[t]);
    int lane = threadIdx.x & 31;
    int q = lane & 7;       // float4 index within 32 batch lanes
    int sub = lane >> 3;    // which of 4 edges this 8-lane group handles
    int warpId = (blockIdx.x * blockDim.x + threadIdx.x) >> 5;
    int nWarp = (gridDim.x * blockDim.x) >> 5;
    float4 acc = make_float4(0.0f, 0.0f, 0.0f, 0.0f);
    for (int e = warpId * 4 + sub; e < nE; e += nWarp * 4) {
        int h = heads[e], tl = tails[e];
        bool fh = g_nz[h] != 0, ft = g_nz[tl] != 0;
        if (fh | ft) {
            int r = rels[e];
            if (fh) {
                float4 xh = x4[h * 8 + q];
                if (xh.x != 0.0f || xh.y != 0.0f || xh.z != 0.0f || xh.w != 0.0f) {
                    float4 w1 = w4[r * 8 + q];
                    float4 m1 = make_float4(xh.x * w1.x, xh.y * w1.y,
                                            xh.z * w1.z, xh.w * w1.w);
                    red_add_v4(&s4[tl * 8 + q], m1);
                    acc.x += m1.x; acc.y += m1.y; acc.z += m1.z; acc.w += m1.w;
                }
            }
            if (ft) {
                float4 xt = x4[tl * 8 + q];
                if (xt.x != 0.0f || xt.y != 0.0f || xt.z != 0.0f || xt.w != 0.0f) {
                    float4 w2 = w4[(r + RSIZEc) * 8 + q];
                    float4 m2 = make_float4(xt.x * w2.x, xt.y * w2.y,
                                            xt.z * w2.z, xt.w * w2.w);
                    red_add_v4(&s4[h * 8 + q], m2);
                    acc.x += m2.x; acc.y += m2.y; acc.z += m2.z; acc.w += m2.w;
                }
            }
        }
    }
    // reduce acc across the 4 lanes sharing each q (xor 8, 16)
    acc.x += __shfl_xor_sync(0xffffffffu, acc.x, 8);
    acc.y += __shfl_xor_sync(0xffffffffu, acc.y, 8);
    acc.z += __shfl_xor_sync(0xffffffffu, acc.z, 8);
    acc.w += __shfl_xor_sync(0xffffffffu, acc.w, 8);
    acc.x += __shfl_xor_sync(0xffffffffu, acc.x, 16);
    acc.y += __shfl_xor_sync(0xffffffffu, acc.y, 16);
    acc.z += __shfl_xor_sync(0xffffffffu, acc.z, 16);
    acc.w += __shfl_xor_sync(0xffffffffu, acc.w, 16);
    __shared__ float sblk[Bsz];
    if (threadIdx.x < Bsz) sblk[threadIdx.x] = 0.0f;
    __syncthreads();
    if (lane < 8) {
        atomicAdd(&sblk[q * 4 + 0], acc.x);
        atomicAdd(&sblk[q * 4 + 1], acc.y);
        atomicAdd(&sblk[q * 4 + 2], acc.z);
        atomicAdd(&sblk[q * 4 + 3], acc.w);
    }
    __syncthreads();
    if (threadIdx.x < Bsz) atomicAdd(&g_sums[threadIdx.x], sblk[threadIdx.x]);
}

__global__ void k_norm(int t) {
    int b = threadIdx.x;
    if (b < Bsz) g_norm[(t + 1) * Bsz + b] = 1.0f / fmaxf(g_sums[b], 1e-7f);
}

// ---------------- final combine + transpose to (B, E) -----------------------
__global__ void k_final(float* __restrict__ out) {
    int tid = blockIdx.x * blockDim.x + threadIdx.x;
    int stride = gridDim.x * blockDim.x;
    int b = tid & 31;
    float a0 = g_attn[0 * Bsz + b];
    float a1 = g_attn[1 * Bsz + b];
    float a2 = g_attn[2 * Bsz + b];
    float a3 = g_attn[3 * Bsz + b];
    for (int j = tid; j < Ecnt * Bsz; j += stride) {
        int e = j >> 5;
        float v = a0 * g_states[0][j] + a1 * g_states[1][j] +
                  a2 * g_states[2][j] + a3 * g_states[3][j];
        out[b * Ecnt + e] = v;
    }
}

// ---------------- launch ----------------------------------------------------
extern "C" void kernel_launch(void* const* d_in, const int* in_sizes, int n_in,
                              void* d_out, int out_size) {
    const int* input_x = (const int*)d_in[0];
    const int* input_r = (const int*)d_in[1];
    const int* heads   = (const int*)d_in[2];
    const int* tails   = (const int*)d_in[3];
    const int* rels    = (const int*)d_in[4];
    const float* emb_W = (const float*)d_in[5];
    const float* W_ih  = (const float*)d_in[6];
    const float* W_hh  = (const float*)d_in[7];
    const float* b_ih  = (const float*)d_in[8];
    const float* b_hh  = (const float*)d_in[9];
    const float* lin_W = (const float*)d_in[10];
    const float* lin_b = (const float*)d_in[11];
    int nE = in_sizes[2];
    float* out = (float*)d_out;

    k_init<<<256, 256>>>();
    k_onehot<<<1, 32>>>(input_x);
    k_transpose<<<128, 256>>>(W_hh, lin_W);
    k_ih<<<4096, 256>>>(emb_W, input_r, W_ih, b_ih, b_hh);
    k_lstm4<<<32, 512>>>();
    k_wsoft<<<96, 128>>>(lin_b);
    for (int t = 0; t < 3; t++) {
        k_att<<<1, 128>>>(t);
        k_inp<<<1184, 256>>>(t);
        k_prop<<<1184, 256>>>(heads, tails, rels, t, nE);
        k_norm<<<1, 32>>>(t);
    }
    k_att<<<1, 128>>>(3);
    k_final<<<1184, 256>>>(out);
}

// round 4
// speedup vs baseline: 1.8014x; 1.0609x over previous
#include <cuda_runtime.h>
#include <math.h>

#define Ecnt 40000
#define Bsz 32
#define Hd 128
#define NRELc 400
#define RSIZEc 200
#define TAU1 10.0f

// ---------------- scratch (static device memory; no allocs) ----------------
// state 0 is virtual (one-hot from input_x); states 1..4 are materialized.
__device__ float g_states[5][Ecnt * Bsz];   // [t][e*32+b]; index 0 unused
__device__ float g_inp[Ecnt * Bsz];         // att-combined input to propagate
__device__ unsigned char g_nz[Ecnt];        // per-entity nonzero flag for g_inp
__device__ float g_rnn[4][Bsz * Hd];        // LSTM hidden per step
__device__ float g_WihT[Hd * 4 * Hd];       // [d][k]
__device__ float g_WhhT[Hd * 4 * Hd];       // [d][k]
__device__ float g_linWT[Hd * NRELc];       // [d][r]
__device__ float g_wT[3][NRELc * Bsz];      // softmaxed relation weights, [t][r*32+b]
__device__ float g_attn[4 * Bsz];           // att premultiplied by norm, [tp*32+b]
__device__ float g_sums[Bsz];
__device__ float g_norm[4 * Bsz];           // 1/max(sum,1e-7) per state (idx 1..3)

__device__ __forceinline__ float sigf(float x) { return 1.0f / (1.0f + expf(-x)); }

__device__ __forceinline__ void red_add_v4(float4* p, float4 v) {
    asm volatile("red.global.add.v4.f32 [%0], {%1, %2, %3, %4};"
                 :: "l"(p), "f"(v.x), "f"(v.y), "f"(v.z), "f"(v.w)
                 : "memory");
}

// ---------------- weight transposes ----------------
__global__ void k_transpose(const float* __restrict__ W_ih,
                            const float* __restrict__ W_hh,
                            const float* __restrict__ lin_W) {
    int i = blockIdx.x * blockDim.x + threadIdx.x;
    int stride = gridDim.x * blockDim.x;
    for (int j = i; j < 4 * Hd * Hd; j += stride) {
        int k = j / Hd, d = j % Hd;
        g_WihT[d * (4 * Hd) + k] = W_ih[j];
        g_WhhT[d * (4 * Hd) + k] = W_hh[j];
    }
    for (int j = i; j < NRELc * Hd; j += stride) {
        int r = j / Hd, d = j % Hd;
        g_linWT[d * NRELc + r] = lin_W[j];
    }
}

// ---------------- full LSTM: ih-pre + 4 steps (32 blocks x 512 thr) --------
__global__ void k_lstm4(const float* __restrict__ emb_W, const int* __restrict__ input_r,
                        const float* __restrict__ b_ih, const float* __restrict__ b_hh) {
    __shared__ float xs0[Hd];
    __shared__ float xs1[Hd];
    __shared__ float hs[Hd];
    __shared__ float cs[Hd];
    __shared__ float gsh[4 * Hd];
    int b = blockIdx.x, k = threadIdx.x;
    if (k < Hd) {
        xs0[k] = emb_W[input_r[b] * Hd + k];
        hs[k] = 0.0f;
        cs[k] = 0.0f;
    } else if (k < 2 * Hd) {
        xs1[k - Hd] = emb_W[NRELc * Hd + (k - Hd)];
    }
    __syncthreads();
    float bias = b_ih[k] + b_hh[k];
    float pre0 = bias, pre1 = bias;
#pragma unroll 8
    for (int d = 0; d < Hd; d++) {
        float w = g_WihT[d * (4 * Hd) + k];
        pre0 += xs0[d] * w;
        pre1 += xs1[d] * w;
    }
#pragma unroll
    for (int t = 0; t < 4; t++) {
        float acc = (t < 3) ? pre0 : pre1;
#pragma unroll 8
        for (int d = 0; d < Hd; d++) acc += hs[d] * g_WhhT[d * (4 * Hd) + k];
        gsh[k] = acc;
        __syncthreads();
        if (k < Hd) {
            float ig = gsh[k], fg = gsh[Hd + k], gg = gsh[2 * Hd + k], og = gsh[3 * Hd + k];
            float c = sigf(fg) * cs[k] + sigf(ig) * tanhf(gg);
            float h = sigf(og) * tanhf(c);
            cs[k] = c;
            hs[k] = h;
            g_rnn[t][b * Hd + k] = h;
        }
        __syncthreads();
    }
}

// ---------------- relation-weight softmax (96 blocks = t*32+b, 128 thr) ----
__global__ void k_wsoft(const float* __restrict__ lin_b) {
    int t = blockIdx.x / Bsz, b = blockIdx.x % Bsz;
    __shared__ float rs[Hd];
    __shared__ float lg[NRELc];
    __shared__ float red[128];
    int tid = threadIdx.x;
    if (tid < Hd) rs[tid] = g_rnn[t][b * Hd + tid];
    __syncthreads();
    float lmax = -1e30f;
    for (int r = tid; r < NRELc; r += 128) {
        float acc = lin_b[r];
        for (int d = 0; d < Hd; d++) acc += rs[d] * g_linWT[d * NRELc + r];
        acc *= TAU1;
        lg[r] = acc;
        lmax = fmaxf(lmax, acc);
    }
    red[tid] = lmax;
    __syncthreads();
    for (int s = 64; s > 0; s >>= 1) {
        if (tid < s) red[tid] = fmaxf(red[tid], red[tid + s]);
        __syncthreads();
    }
    float m = red[0];
    __syncthreads();
    float lsum = 0.0f;
    for (int r = tid; r < NRELc; r += 128) {
        float e = expf(lg[r] - m);
        lg[r] = e;
        lsum += e;
    }
    red[tid] = lsum;
    __syncthreads();
    for (int s = 64; s > 0; s >>= 1) {
        if (tid < s) red[tid] += red[tid + s];
        __syncthreads();
    }
    float inv = 1.0f / red[0];
    for (int r = tid; r < NRELc; r += 128) g_wT[t][r * Bsz + b] = lg[r] * inv;
}

// ---------------- attention + norm of latest state (1 block, 128 thr) ------
__global__ void k_att(int t) {
    __shared__ float lg[Bsz][4];
    int tid = threadIdx.x;
    int b = tid >> 2, tp = tid & 3;
    float v = 0.0f;
    if (tp <= t) {
        for (int d = 0; d < Hd; d++) v += g_rnn[t][b * Hd + d] * g_rnn[tp][b * Hd + d];
    }
    lg[b][tp] = v;
    __syncthreads();
    if (tid < Bsz) {
        int b2 = tid;
        // finalize normalization of the state produced by prop(t-1)
        float nt = 1.0f;
        if (t >= 1) {
            nt = 1.0f / fmaxf(g_sums[b2], 1e-7f);
            g_norm[t * Bsz + b2] = nt;
        }
        float m = -1e30f;
        for (int j = 0; j <= t; j++) m = fmaxf(m, lg[b2][j]);
        float s = 0.0f, e[4];
        for (int j = 0; j <= t; j++) { e[j] = expf(lg[b2][j] - m); s += e[j]; }
        float inv = 1.0f / s;
        for (int j = 0; j <= t; j++) {
            float nj = (j == 0) ? 1.0f : ((j == t) ? nt : g_norm[j * Bsz + b2]);
            g_attn[j * Bsz + b2] = e[j] * inv * nj;
        }
        for (int j = t + 1; j < 4; j++) g_attn[j * Bsz + b2] = 0.0f;
        g_sums[b2] = 0.0f;  // reset for the upcoming propagation's reduction
    }
}

// ---------------- combine states -> g_inp, nz flags, zero next state -------
__global__ void k_inp(const int* __restrict__ input_x, int t) {
    int tid = blockIdx.x * blockDim.x + threadIdx.x;
    int stride = gridDim.x * blockDim.x;
    int q = tid & 7;
    const float4* __restrict__ a4 = reinterpret_cast<const float4*>(g_attn);
    float4 a0 = a4[0 * 8 + q];
    float4 a1 = a4[1 * 8 + q];
    float4 a2 = a4[2 * 8 + q];
    int4 xi = reinterpret_cast<const int4*>(input_x)[q];
    const float4* __restrict__ s1 = reinterpret_cast<const float4*>(g_states[1]);
    const float4* __restrict__ s2 = reinterpret_cast<const float4*>(g_states[2]);
    float4* inp4 = reinterpret_cast<float4*>(g_inp);
    float4* snew = reinterpret_cast<float4*>(g_states[t + 1]);
    const float4 z = make_float4(0.0f, 0.0f, 0.0f, 0.0f);
    int lane = threadIdx.x & 31;
    int grp = lane >> 3;
    for (int u = tid; u < Ecnt * 8; u += stride) {
        int e = u >> 3;
        float4 v = make_float4(xi.x == e ? a0.x : 0.0f, xi.y == e ? a0.y : 0.0f,
                               xi.z == e ? a0.z : 0.0f, xi.w == e ? a0.w : 0.0f);
        if (t >= 1) {
            float4 s = s1[u];
            v.x += a1.x * s.x; v.y += a1.y * s.y; v.z += a1.z * s.z; v.w += a1.w * s.w;
        }
        if (t >= 2) {
            float4 s = s2[u];
            v.x += a2.x * s.x; v.y += a2.y * s.y; v.z += a2.z * s.z; v.w += a2.w * s.w;
        }
        inp4[u] = v;
        snew[u] = z;
        bool nzv = (v.x != 0.0f) | (v.y != 0.0f) | (v.z != 0.0f) | (v.w != 0.0f);
        unsigned m = __ballot_sync(0xffffffffu, nzv);
        if ((lane & 7) == 0) g_nz[e] = ((m >> (grp * 8)) & 0xffu) ? 1 : 0;
    }
}

// ---------------- propagate: sparse-aware, fused batch sums ----------------
__global__ void k_prop(const int* __restrict__ heads, const int* __restrict__ tails,
                       const int* __restrict__ rels, int t, int nE) {
    const float4* __restrict__ x4 = reinterpret_cast<const float4*>(g_inp);
    float4* s4 = reinterpret_cast<float4*>(g_states[t + 1]);
    const float4* __restrict__ w4 = reinterpret_cast<const float4*>(g_wT[t]);
    int lane = threadIdx.x & 31;
    int q = lane & 7;       // float4 index within 32 batch lanes
    int sub = lane >> 3;    // which of 4 edges this 8-lane group handles
    int warpId = (blockIdx.x * blockDim.x + threadIdx.x) >> 5;
    int nWarp = (gridDim.x * blockDim.x) >> 5;
    float4 acc = make_float4(0.0f, 0.0f, 0.0f, 0.0f);
    for (int e = warpId * 4 + sub; e < nE; e += nWarp * 4) {
        int h = heads[e], tl = tails[e];
        bool fh = g_nz[h] != 0, ft = g_nz[tl] != 0;
        if (fh | ft) {
            int r = rels[e];
            if (fh) {
                float4 xh = x4[h * 8 + q];
                if (xh.x != 0.0f || xh.y != 0.0f || xh.z != 0.0f || xh.w != 0.0f) {
                    float4 w1 = w4[r * 8 + q];
                    float4 m1 = make_float4(xh.x * w1.x, xh.y * w1.y,
                                            xh.z * w1.z, xh.w * w1.w);
                    red_add_v4(&s4[tl * 8 + q], m1);
                    acc.x += m1.x; acc.y += m1.y; acc.z += m1.z; acc.w += m1.w;
                }
            }
            if (ft) {
                float4 xt = x4[tl * 8 + q];
                if (xt.x != 0.0f || xt.y != 0.0f || xt.z != 0.0f || xt.w != 0.0f) {
                    float4 w2 = w4[(r + RSIZEc) * 8 + q];
                    float4 m2 = make_float4(xt.x * w2.x, xt.y * w2.y,
                                            xt.z * w2.z, xt.w * w2.w);
                    red_add_v4(&s4[h * 8 + q], m2);
                    acc.x += m2.x; acc.y += m2.y; acc.z += m2.z; acc.w += m2.w;
                }
            }
        }
    }
    acc.x += __shfl_xor_sync(0xffffffffu, acc.x, 8);
    acc.y += __shfl_xor_sync(0xffffffffu, acc.y, 8);
    acc.z += __shfl_xor_sync(0xffffffffu, acc.z, 8);
    acc.w += __shfl_xor_sync(0xffffffffu, acc.w, 8);
    acc.x += __shfl_xor_sync(0xffffffffu, acc.x, 16);
    acc.y += __shfl_xor_sync(0xffffffffu, acc.y, 16);
    acc.z += __shfl_xor_sync(0xffffffffu, acc.z, 16);
    acc.w += __shfl_xor_sync(0xffffffffu, acc.w, 16);
    __shared__ float sblk[Bsz];
    if (threadIdx.x < Bsz) sblk[threadIdx.x] = 0.0f;
    __syncthreads();
    if (lane < 8) {
        atomicAdd(&sblk[q * 4 + 0], acc.x);
        atomicAdd(&sblk[q * 4 + 1], acc.y);
        atomicAdd(&sblk[q * 4 + 2], acc.z);
        atomicAdd(&sblk[q * 4 + 3], acc.w);
    }
    __syncthreads();
    if (threadIdx.x < Bsz) atomicAdd(&g_sums[threadIdx.x], sblk[threadIdx.x]);
}

// ---------------- final combine, tiled transpose to (B, E) ------------------
__global__ void k_final(const int* __restrict__ input_x, float* __restrict__ out) {
    __shared__ float tile[32][33];
    int e0 = blockIdx.x * 32;
    int r = threadIdx.x >> 3, q = threadIdx.x & 7;
    const float4* __restrict__ a4 = reinterpret_cast<const float4*>(g_attn);
    float4 a0 = a4[0 * 8 + q];
    float4 a1 = a4[1 * 8 + q];
    float4 a2 = a4[2 * 8 + q];
    float4 a3 = a4[3 * 8 + q];
    int4 xi = reinterpret_cast<const int4*>(input_x)[q];
    const float4* __restrict__ s1 = reinterpret_cast<const float4*>(g_states[1]);
    const float4* __restrict__ s2 = reinterpret_cast<const float4*>(g_states[2]);
    const float4* __restrict__ s3 = reinterpret_cast<const float4*>(g_states[3]);
    int e = e0 + r;
    int u = e * 8 + q;
    float4 v1 = s1[u], v2 = s2[u], v3 = s3[u];
    float4 v;
    v.x = (xi.x == e ? a0.x : 0.0f) + a1.x * v1.x + a2.x * v2.x + a3.x * v3.x;
    v.y = (xi.y == e ? a0.y : 0.0f) + a1.y * v1.y + a2.y * v2.y + a3.y * v3.y;
    v.z = (xi.z == e ? a0.z : 0.0f) + a1.z * v1.z + a2.z * v2.z + a3.z * v3.z;
    v.w = (xi.w == e ? a0.w : 0.0f) + a1.w * v1.w + a2.w * v2.w + a3.w * v3.w;
    tile[r][4 * q + 0] = v.x;
    tile[r][4 * q + 1] = v.y;
    tile[r][4 * q + 2] = v.z;
    tile[r][4 * q + 3] = v.w;
    __syncthreads();
    int w = threadIdx.x >> 5, lane = threadIdx.x & 31;
#pragma unroll
    for (int bb = 0; bb < 4; bb++) {
        int b = w * 4 + bb;
        out[b * Ecnt + e0 + lane] = tile[lane][b];
    }
}

// ---------------- launch ----------------------------------------------------
extern "C" void kernel_launch(void* const* d_in, const int* in_sizes, int n_in,
                              void* d_out, int out_size) {
    const int* input_x = (const int*)d_in[0];
    const int* input_r = (const int*)d_in[1];
    const int* heads   = (const int*)d_in[2];
    const int* tails   = (const int*)d_in[3];
    const int* rels    = (const int*)d_in[4];
    const float* emb_W = (const float*)d_in[5];
    const float* W_ih  = (const float*)d_in[6];
    const float* W_hh  = (const float*)d_in[7];
    const float* b_ih  = (const float*)d_in[8];
    const float* b_hh  = (const float*)d_in[9];
    const float* lin_W = (const float*)d_in[10];
    const float* lin_b = (const float*)d_in[11];
    int nE = in_sizes[2];
    float* out = (float*)d_out;

    k_transpose<<<128, 256>>>(W_ih, W_hh, lin_W);
    k_lstm4<<<32, 512>>>(emb_W, input_r, b_ih, b_hh);
    k_wsoft<<<96, 128>>>(lin_b);
    for (int t = 0; t < 3; t++) {
        k_att<<<1, 128>>>(t);
        k_inp<<<1184, 256>>>(input_x, t);
        k_prop<<<1184, 256>>>(heads, tails, rels, t, nE);
    }
    k_att<<<1, 128>>>(3);
    k_final<<<1250, 256>>>(input_x, out);
}

// round 5
// speedup vs baseline: 2.2929x; 1.2729x over previous
#include <cuda_runtime.h>
#include <math.h>

#define Ecnt 40000
#define Bsz 32
#define Hd 128
#define NRELc 400
#define RSIZEc 200
#define TAU1 10.0f

// ---------------- scratch (static device memory; no allocs) ----------------
// state 0 is virtual (one-hot from input_x); states 1..4 are materialized.
__device__ float g_states[5][Ecnt * Bsz];   // [t][e*32+b]; index 0 unused
__device__ float g_inp[Ecnt * Bsz];         // att-combined input to propagate
__device__ unsigned char g_nz[Ecnt];        // per-entity nonzero flag for g_inp
__device__ float g_rnn[4][Bsz * Hd];        // LSTM hidden per step
__device__ float g_logits[4][4][Bsz];       // raw attention logits [t][tp][b]
__device__ float g_eatt[4][4][Bsz];         // softmaxed attention   [t][tp][b]
__device__ float g_WihT[Hd * 4 * Hd];       // [d][k]
__device__ float g_WhhT[Hd * 4 * Hd];       // [d][k]
__device__ float g_linWT[Hd * NRELc];       // [d][r]
__device__ float g_wT[3][NRELc * Bsz];      // softmaxed relation weights, [t][r*32+b]
__device__ float g_sums[3][Bsz];            // per-prop-step message sums

__device__ __forceinline__ float sigf(float x) { return 1.0f / (1.0f + expf(-x)); }

__device__ __forceinline__ void red_add_v4(float4* p, float4 v) {
    asm volatile("red.global.add.v4.f32 [%0], {%1, %2, %3, %4};"
                 :: "l"(p), "f"(v.x), "f"(v.y), "f"(v.z), "f"(v.w)
                 : "memory");
}

// ---------------- weight transposes + sums reset ----------------
__global__ void k_transpose(const float* __restrict__ W_ih,
                            const float* __restrict__ W_hh,
                            const float* __restrict__ lin_W) {
    int i = blockIdx.x * blockDim.x + threadIdx.x;
    int stride = gridDim.x * blockDim.x;
    if (i < 3 * Bsz) ((float*)g_sums)[i] = 0.0f;
    for (int j = i; j < 4 * Hd * Hd; j += stride) {
        int k = j / Hd, d = j % Hd;
        g_WihT[d * (4 * Hd) + k] = W_ih[j];
        g_WhhT[d * (4 * Hd) + k] = W_hh[j];
    }
    for (int j = i; j < NRELc * Hd; j += stride) {
        int r = j / Hd, d = j % Hd;
        g_linWT[d * NRELc + r] = lin_W[j];
    }
}

// ---------------- LSTM: ih-pre + 4 steps + attention logits ----------------
__global__ void k_lstm4(const float* __restrict__ emb_W, const int* __restrict__ input_r,
                        const float* __restrict__ b_ih, const float* __restrict__ b_hh) {
    __shared__ float xs0[Hd];
    __shared__ float xs1[Hd];
    __shared__ float cs[Hd];
    __shared__ float gsh[4 * Hd];
    __shared__ float hist[4][Hd];
    int b = blockIdx.x, k = threadIdx.x;
    if (k < Hd) {
        xs0[k] = emb_W[input_r[b] * Hd + k];
        cs[k] = 0.0f;
        hist[3][k] = 0.0f;  // used as "current h" seed via pointer trick below
    } else if (k < 2 * Hd) {
        xs1[k - Hd] = emb_W[NRELc * Hd + (k - Hd)];
    }
    __syncthreads();
    float bias = b_ih[k] + b_hh[k];
    float pre0 = bias, pre1 = bias;
#pragma unroll 8
    for (int d = 0; d < Hd; d++) {
        float w = g_WihT[d * (4 * Hd) + k];
        pre0 += xs0[d] * w;
        pre1 += xs1[d] * w;
    }
#pragma unroll
    for (int t = 0; t < 4; t++) {
        const float* hprev = (t == 0) ? hist[3] : hist[t - 1];
        float acc = (t < 3) ? pre0 : pre1;
#pragma unroll 8
        for (int d = 0; d < Hd; d++) acc += hprev[d] * g_WhhT[d * (4 * Hd) + k];
        gsh[k] = acc;
        __syncthreads();
        if (k < Hd) {
            float ig = gsh[k], fg = gsh[Hd + k], gg = gsh[2 * Hd + k], og = gsh[3 * Hd + k];
            float c = sigf(fg) * cs[k] + sigf(ig) * tanhf(gg);
            float h = sigf(og) * tanhf(c);
            cs[k] = c;
            hist[t][k] = h;
            g_rnn[t][b * Hd + k] = h;
        }
        __syncthreads();
    }
    // attention logits: 16 warps, warp w = (t,tp)
    int w = k >> 5, lane = k & 31;
    int t = w >> 2, tp = w & 3;
    if (tp <= t) {
        float acc = 0.0f;
#pragma unroll
        for (int i = 0; i < 4; i++) {
            int d = lane + 32 * i;
            acc += hist[t][d] * hist[tp][d];
        }
#pragma unroll
        for (int s = 16; s > 0; s >>= 1) acc += __shfl_xor_sync(0xffffffffu, acc, s);
        if (lane == 0) g_logits[t][tp][b] = acc;
    }
}

// ---------------- relation-weight softmax + attention softmax --------------
__global__ void k_wsoft(const float* __restrict__ lin_b) {
    __shared__ float rs[Hd];
    __shared__ float lg[NRELc];
    __shared__ float red[128];
    int tid = threadIdx.x;
    if (blockIdx.x >= 96) {
        // attention softmax: 128 threads = (t, b)
        int t = tid >> 5, b = tid & 31;
        float m = -1e30f;
        float l[4];
        for (int j = 0; j <= t; j++) { l[j] = g_logits[t][j][b]; m = fmaxf(m, l[j]); }
        float s = 0.0f;
        for (int j = 0; j <= t; j++) { l[j] = expf(l[j] - m); s += l[j]; }
        float inv = 1.0f / s;
        for (int j = 0; j < 4; j++)
            g_eatt[t][j][b] = (j <= t) ? l[j] * inv : 0.0f;
        return;
    }
    int t = blockIdx.x / Bsz, b = blockIdx.x % Bsz;
    if (tid < Hd) rs[tid] = g_rnn[t][b * Hd + tid];
    __syncthreads();
    float lmax = -1e30f;
    for (int r = tid; r < NRELc; r += 128) {
        float acc = lin_b[r];
        for (int d = 0; d < Hd; d++) acc += rs[d] * g_linWT[d * NRELc + r];
        acc *= TAU1;
        lg[r] = acc;
        lmax = fmaxf(lmax, acc);
    }
    red[tid] = lmax;
    __syncthreads();
    for (int s = 64; s > 0; s >>= 1) {
        if (tid < s) red[tid] = fmaxf(red[tid], red[tid + s]);
        __syncthreads();
    }
    float m = red[0];
    __syncthreads();
    float lsum = 0.0f;
    for (int r = tid; r < NRELc; r += 128) {
        float e = expf(lg[r] - m);
        lg[r] = e;
        lsum += e;
    }
    red[tid] = lsum;
    __syncthreads();
    for (int s = 64; s > 0; s >>= 1) {
        if (tid < s) red[tid] += red[tid + s];
        __syncthreads();
    }
    float inv = 1.0f / red[0];
    for (int r = tid; r < NRELc; r += 128) g_wT[t][r * Bsz + b] = lg[r] * inv;
}

// norm for state j (j>=1) = 1/max(g_sums[j-1][b], 1e-7); state 0 norm = 1
__device__ __forceinline__ float4 attn_vec(int t, int j, int q) {
    float4 e = reinterpret_cast<const float4*>(g_eatt)[(t * 4 + j) * 8 + q];
    if (j >= 1) {
        float4 s = reinterpret_cast<const float4*>(g_sums)[(j - 1) * 8 + q];
        e.x *= 1.0f / fmaxf(s.x, 1e-7f);
        e.y *= 1.0f / fmaxf(s.y, 1e-7f);
        e.z *= 1.0f / fmaxf(s.z, 1e-7f);
        e.w *= 1.0f / fmaxf(s.w, 1e-7f);
    }
    return e;
}

// ---------------- combine states -> g_inp, nz flags, zero next state -------
__global__ void k_inp(const int* __restrict__ input_x, int t) {
    int tid = blockIdx.x * blockDim.x + threadIdx.x;
    int stride = gridDim.x * blockDim.x;
    int q = tid & 7;
    float4 a0 = attn_vec(t, 0, q);
    float4 a1 = attn_vec(t, 1, q);
    float4 a2 = (t >= 2) ? attn_vec(t, 2, q) : make_float4(0, 0, 0, 0);
    int4 xi = reinterpret_cast<const int4*>(input_x)[q];
    const float4* __restrict__ s1 = reinterpret_cast<const float4*>(g_states[1]);
    const float4* __restrict__ s2 = reinterpret_cast<const float4*>(g_states[2]);
    float4* inp4 = reinterpret_cast<float4*>(g_inp);
    float4* snew = reinterpret_cast<float4*>(g_states[t + 1]);
    const float4 z = make_float4(0.0f, 0.0f, 0.0f, 0.0f);
    int lane = threadIdx.x & 31;
    int grp = lane >> 3;
    for (int u = tid; u < Ecnt * 8; u += stride) {
        int e = u >> 3;
        float4 v = make_float4(xi.x == e ? a0.x : 0.0f, xi.y == e ? a0.y : 0.0f,
                               xi.z == e ? a0.z : 0.0f, xi.w == e ? a0.w : 0.0f);
        if (t >= 1) {
            float4 s = s1[u];
            v.x += a1.x * s.x; v.y += a1.y * s.y; v.z += a1.z * s.z; v.w += a1.w * s.w;
        }
        if (t >= 2) {
            float4 s = s2[u];
            v.x += a2.x * s.x; v.y += a2.y * s.y; v.z += a2.z * s.z; v.w += a2.w * s.w;
        }
        inp4[u] = v;
        snew[u] = z;
        bool nzv = (v.x != 0.0f) | (v.y != 0.0f) | (v.z != 0.0f) | (v.w != 0.0f);
        unsigned m = __ballot_sync(0xffffffffu, nzv);
        if ((lane & 7) == 0) g_nz[e] = ((m >> (grp * 8)) & 0xffu) ? 1 : 0;
    }
}

// ---------------- propagate: sparse-aware, fused batch sums ----------------
__global__ void k_prop(const int* __restrict__ heads, const int* __restrict__ tails,
                       const int* __restrict__ rels, int t, int nE) {
    const float4* __restrict__ x4 = reinterpret_cast<const float4*>(g_inp);
    float4* s4 = reinterpret_cast<float4*>(g_states[t + 1]);
    const float4* __restrict__ w4 = reinterpret_cast<const float4*>(g_wT[t]);
    int lane = threadIdx.x & 31;
    int q = lane & 7;
    int sub = lane >> 3;
    int warpId = (blockIdx.x * blockDim.x + threadIdx.x) >> 5;
    int nWarp = (gridDim.x * blockDim.x) >> 5;
    float4 acc = make_float4(0.0f, 0.0f, 0.0f, 0.0f);
    for (int e = warpId * 4 + sub; e < nE; e += nWarp * 4) {
        int h = heads[e], tl = tails[e];
        bool fh = g_nz[h] != 0, ft = g_nz[tl] != 0;
        if (fh | ft) {
            int r = rels[e];
            if (fh) {
                float4 xh = x4[h * 8 + q];
                if (xh.x != 0.0f || xh.y != 0.0f || xh.z != 0.0f || xh.w != 0.0f) {
                    float4 w1 = w4[r * 8 + q];
                    float4 m1 = make_float4(xh.x * w1.x, xh.y * w1.y,
                                            xh.z * w1.z, xh.w * w1.w);
                    red_add_v4(&s4[tl * 8 + q], m1);
                    acc.x += m1.x; acc.y += m1.y; acc.z += m1.z; acc.w += m1.w;
                }
            }
            if (ft) {
                float4 xt = x4[tl * 8 + q];
                if (xt.x != 0.0f || xt.y != 0.0f || xt.z != 0.0f || xt.w != 0.0f) {
                    float4 w2 = w4[(r + RSIZEc) * 8 + q];
                    float4 m2 = make_float4(xt.x * w2.x, xt.y * w2.y,
                                            xt.z * w2.z, xt.w * w2.w);
                    red_add_v4(&s4[h * 8 + q], m2);
                    acc.x += m2.x; acc.y += m2.y; acc.z += m2.z; acc.w += m2.w;
                }
            }
        }
    }
    acc.x += __shfl_xor_sync(0xffffffffu, acc.x, 8);
    acc.y += __shfl_xor_sync(0xffffffffu, acc.y, 8);
    acc.z += __shfl_xor_sync(0xffffffffu, acc.z, 8);
    acc.w += __shfl_xor_sync(0xffffffffu, acc.w, 8);
    acc.x += __shfl_xor_sync(0xffffffffu, acc.x, 16);
    acc.y += __shfl_xor_sync(0xffffffffu, acc.y, 16);
    acc.z += __shfl_xor_sync(0xffffffffu, acc.z, 16);
    acc.w += __shfl_xor_sync(0xffffffffu, acc.w, 16);
    __shared__ float sblk[Bsz];
    if (threadIdx.x < Bsz) sblk[threadIdx.x] = 0.0f;
    __syncthreads();
    if (lane < 8) {
        atomicAdd(&sblk[q * 4 + 0], acc.x);
        atomicAdd(&sblk[q * 4 + 1], acc.y);
        atomicAdd(&sblk[q * 4 + 2], acc.z);
        atomicAdd(&sblk[q * 4 + 3], acc.w);
    }
    __syncthreads();
    if (threadIdx.x < Bsz) atomicAdd(&g_sums[t][threadIdx.x], sblk[threadIdx.x]);
}

// ---------------- final combine, tiled transpose to (B, E) ------------------
__global__ void k_final(const int* __restrict__ input_x, float* __restrict__ out) {
    __shared__ float tile[32][33];
    int e0 = blockIdx.x * 32;
    int r = threadIdx.x >> 3, q = threadIdx.x & 7;
    float4 a0 = attn_vec(3, 0, q);
    float4 a1 = attn_vec(3, 1, q);
    float4 a2 = attn_vec(3, 2, q);
    float4 a3 = attn_vec(3, 3, q);
    int4 xi = reinterpret_cast<const int4*>(input_x)[q];
    const float4* __restrict__ s1 = reinterpret_cast<const float4*>(g_states[1]);
    const float4* __restrict__ s2 = reinterpret_cast<const float4*>(g_states[2]);
    const float4* __restrict__ s3 = reinterpret_cast<const float4*>(g_states[3]);
    int e = e0 + r;
    int u = e * 8 + q;
    float4 v1 = s1[u], v2 = s2[u], v3 = s3[u];
    float4 v;
    v.x = (xi.x == e ? a0.x : 0.0f) + a1.x * v1.x + a2.x * v2.x + a3.x * v3.x;
    v.y = (xi.y == e ? a0.y : 0.0f) + a1.y * v1.y + a2.y * v2.y + a3.y * v3.y;
    v.z = (xi.z == e ? a0.z : 0.0f) + a1.z * v1.z + a2.z * v2.z + a3.z * v3.z;
    v.w = (xi.w == e ? a0.w : 0.0f) + a1.w * v1.w + a2.w * v2.w + a3.w * v3.w;
    tile[r][4 * q + 0] = v.x;
    tile[r][4 * q + 1] = v.y;
    tile[r][4 * q + 2] = v.z;
    tile[r][4 * q + 3] = v.w;
    __syncthreads();
    int w = threadIdx.x >> 5, lane = threadIdx.x & 31;
#pragma unroll
    for (int bb = 0; bb < 4; bb++) {
        int b = w * 4 + bb;
        out[b * Ecnt + e0 + lane] = tile[lane][b];
    }
}

// ---------------- launch ----------------------------------------------------
extern "C" void kernel_launch(void* const* d_in, const int* in_sizes, int n_in,
                              void* d_out, int out_size) {
    const int* input_x = (const int*)d_in[0];
    const int* input_r = (const int*)d_in[1];
    const int* heads   = (const int*)d_in[2];
    const int* tails   = (const int*)d_in[3];
    const int* rels    = (const int*)d_in[4];
    const float* emb_W = (const float*)d_in[5];
    const float* W_ih  = (const float*)d_in[6];
    const float* W_hh  = (const float*)d_in[7];
    const float* b_ih  = (const float*)d_in[8];
    const float* b_hh  = (const float*)d_in[9];
    const float* lin_W = (const float*)d_in[10];
    const float* lin_b = (const float*)d_in[11];
    int nE = in_sizes[2];
    float* out = (float*)d_out;

    k_transpose<<<128, 256>>>(W_ih, W_hh, lin_W);
    k_lstm4<<<32, 512>>>(emb_W, input_r, b_ih, b_hh);
    k_wsoft<<<97, 128>>>(lin_b);
    for (int t = 0; t < 3; t++) {
        k_inp<<<1184, 256>>>(input_x, t);
        k_prop<<<1184, 256>>>(heads, tails, rels, t, nE);
    }
    k_final<<<1250, 256>>>(input_x, out);
}

// round 6
// speedup vs baseline: 2.3085x; 1.0068x over previous
#include <cuda_runtime.h>
#include <math.h>

#define Ecnt 40000
#define Bsz 32
#define Hd 128
#define NRELc 400
#define RSIZEc 200
#define TAU1 10.0f

// ---------------- scratch (static device memory; no allocs) ----------------
// state 0 is virtual (one-hot from input_x); states 1..3 are materialized.
__device__ float g_states[4][Ecnt * Bsz];   // [t][e*32+b]; index 0 unused
__device__ float g_inp[Ecnt * Bsz];         // att-combined input to propagate
__device__ unsigned char g_nz[Ecnt];        // per-entity nonzero flag for g_inp
__device__ float g_rnn[4][Bsz * Hd];        // LSTM hidden per step
__device__ float g_logits[4][4][Bsz];       // raw attention logits [t][tp][b]
__device__ float g_eatt[4][4][Bsz];         // softmaxed attention   [t][tp][b]
__device__ float g_WihT[Hd * 4 * Hd];       // [d][k]
__device__ float g_WhhT[Hd * 4 * Hd];       // [d][k]
__device__ float g_linWT[Hd * NRELc];       // [d][r]
__device__ float g_wT[3][NRELc * Bsz];      // softmaxed relation weights, [t][r*32+b]
__device__ float g_sums[3][Bsz];            // per-prop-step message sums

__device__ __forceinline__ float sigf(float x) { return 1.0f / (1.0f + expf(-x)); }

__device__ __forceinline__ void red_add_v4(float4* p, float4 v) {
    asm volatile("red.global.add.v4.f32 [%0], {%1, %2, %3, %4};"
                 :: "l"(p), "f"(v.x), "f"(v.y), "f"(v.z), "f"(v.w)
                 : "memory");
}

// ---------------- pre: zero everything + weight transposes ----------------
__global__ void k_pre(const float* __restrict__ W_ih,
                      const float* __restrict__ W_hh,
                      const float* __restrict__ lin_W) {
    int i = blockIdx.x * blockDim.x + threadIdx.x;
    int stride = gridDim.x * blockDim.x;
    const float4 z = make_float4(0.0f, 0.0f, 0.0f, 0.0f);
    float4* s4 = reinterpret_cast<float4*>(g_states[1]);   // states 1..3 contiguous
    float4* i4 = reinterpret_cast<float4*>(g_inp);
    for (int j = i; j < 3 * Ecnt * 8; j += stride) s4[j] = z;
    for (int j = i; j < Ecnt * 8; j += stride) i4[j] = z;
    for (int j = i; j < Ecnt / 4; j += stride) reinterpret_cast<int*>(g_nz)[j] = 0;
    if (i < 3 * Bsz) ((float*)g_sums)[i] = 0.0f;
    for (int j = i; j < 4 * Hd * Hd; j += stride) {
        int k = j / Hd, d = j % Hd;
        g_WihT[d * (4 * Hd) + k] = W_ih[j];
        g_WhhT[d * (4 * Hd) + k] = W_hh[j];
    }
    for (int j = i; j < NRELc * Hd; j += stride) {
        int r = j / Hd, d = j % Hd;
        g_linWT[d * NRELc + r] = lin_W[j];
    }
}

// ---------------- seed t=0 propagation input (weight is exactly 1.0) -------
__global__ void k_seed(const int* __restrict__ input_x) {
    int b = threadIdx.x;
    if (b < Bsz) {
        int e = input_x[b];
        g_inp[e * Bsz + b] = 1.0f;
        g_nz[e] = 1;
    }
}

// ---------------- LSTM: ih-pre + 4 steps + attention logits ----------------
__global__ void k_lstm4(const float* __restrict__ emb_W, const int* __restrict__ input_r,
                        const float* __restrict__ b_ih, const float* __restrict__ b_hh) {
    __shared__ float xs0[Hd];
    __shared__ float xs1[Hd];
    __shared__ float cs[Hd];
    __shared__ float gsh[4 * Hd];
    __shared__ float hist[4][Hd];
    int b = blockIdx.x, k = threadIdx.x;
    if (k < Hd) {
        xs0[k] = emb_W[input_r[b] * Hd + k];
        cs[k] = 0.0f;
        hist[3][k] = 0.0f;  // h seed for t=0 via hprev pointer below
    } else if (k < 2 * Hd) {
        xs1[k - Hd] = emb_W[NRELc * Hd + (k - Hd)];
    }
    __syncthreads();
    float bias = b_ih[k] + b_hh[k];
    float pre0 = bias, pre1 = bias;
#pragma unroll 8
    for (int d = 0; d < Hd; d++) {
        float w = g_WihT[d * (4 * Hd) + k];
        pre0 += xs0[d] * w;
        pre1 += xs1[d] * w;
    }
#pragma unroll
    for (int t = 0; t < 4; t++) {
        const float* hprev = (t == 0) ? hist[3] : hist[t - 1];
        float acc = (t < 3) ? pre0 : pre1;
#pragma unroll 8
        for (int d = 0; d < Hd; d++) acc += hprev[d] * g_WhhT[d * (4 * Hd) + k];
        gsh[k] = acc;
        __syncthreads();
        if (k < Hd) {
            float ig = gsh[k], fg = gsh[Hd + k], gg = gsh[2 * Hd + k], og = gsh[3 * Hd + k];
            float c = sigf(fg) * cs[k] + sigf(ig) * tanhf(gg);
            float h = sigf(og) * tanhf(c);
            cs[k] = c;
            hist[t][k] = h;
            g_rnn[t][b * Hd + k] = h;
        }
        __syncthreads();
    }
    // attention logits: 16 warps, warp w = (t,tp)
    int w = k >> 5, lane = k & 31;
    int t = w >> 2, tp = w & 3;
    if (tp <= t) {
        float acc = 0.0f;
#pragma unroll
        for (int i = 0; i < 4; i++) {
            int d = lane + 32 * i;
            acc += hist[t][d] * hist[tp][d];
        }
#pragma unroll
        for (int s = 16; s > 0; s >>= 1) acc += __shfl_xor_sync(0xffffffffu, acc, s);
        if (lane == 0) g_logits[t][tp][b] = acc;
    }
}

// ---------------- relation-weight softmax + attention softmax --------------
__global__ void k_wsoft(const float* __restrict__ lin_b) {
    __shared__ float rs[Hd];
    __shared__ float lg[NRELc];
    __shared__ float red[128];
    int tid = threadIdx.x;
    if (blockIdx.x >= 96) {
        int t = tid >> 5, b = tid & 31;
        float m = -1e30f;
        float l[4];
        for (int j = 0; j <= t; j++) { l[j] = g_logits[t][j][b]; m = fmaxf(m, l[j]); }
        float s = 0.0f;
        for (int j = 0; j <= t; j++) { l[j] = expf(l[j] - m); s += l[j]; }
        float inv = 1.0f / s;
        for (int j = 0; j < 4; j++)
            g_eatt[t][j][b] = (j <= t) ? l[j] * inv : 0.0f;
        return;
    }
    int t = blockIdx.x / Bsz, b = blockIdx.x % Bsz;
    if (tid < Hd) rs[tid] = g_rnn[t][b * Hd + tid];
    __syncthreads();
    float lmax = -1e30f;
    for (int r = tid; r < NRELc; r += 128) {
        float acc = lin_b[r];
        for (int d = 0; d < Hd; d++) acc += rs[d] * g_linWT[d * NRELc + r];
        acc *= TAU1;
        lg[r] = acc;
        lmax = fmaxf(lmax, acc);
    }
    red[tid] = lmax;
    __syncthreads();
    for (int s = 64; s > 0; s >>= 1) {
        if (tid < s) red[tid] = fmaxf(red[tid], red[tid + s]);
        __syncthreads();
    }
    float m = red[0];
    __syncthreads();
    float lsum = 0.0f;
    for (int r = tid; r < NRELc; r += 128) {
        float e = expf(lg[r] - m);
        lg[r] = e;
        lsum += e;
    }
    red[tid] = lsum;
    __syncthreads();
    for (int s = 64; s > 0; s >>= 1) {
        if (tid < s) red[tid] += red[tid + s];
        __syncthreads();
    }
    float inv = 1.0f / red[0];
    for (int r = tid; r < NRELc; r += 128) g_wT[t][r * Bsz + b] = lg[r] * inv;
}

// norm for state j (j>=1) = 1/max(g_sums[j-1][b], 1e-7); state 0 norm = 1
__device__ __forceinline__ float4 attn_vec(int t, int j, int q) {
    float4 e = reinterpret_cast<const float4*>(g_eatt)[(t * 4 + j) * 8 + q];
    if (j >= 1) {
        float4 s = reinterpret_cast<const float4*>(g_sums)[(j - 1) * 8 + q];
        e.x *= 1.0f / fmaxf(s.x, 1e-7f);
        e.y *= 1.0f / fmaxf(s.y, 1e-7f);
        e.z *= 1.0f / fmaxf(s.z, 1e-7f);
        e.w *= 1.0f / fmaxf(s.w, 1e-7f);
    }
    return e;
}

// ---------------- combine states -> g_inp + nz flags (t = 1 or 2) ----------
// exact cover: grid*block == Ecnt*8, one float4 per thread, no loop
__global__ void k_inp(const int* __restrict__ input_x, int t) {
    int u = blockIdx.x * blockDim.x + threadIdx.x;
    int q = u & 7;
    float4 a0 = attn_vec(t, 0, q);
    float4 a1 = attn_vec(t, 1, q);
    float4 a2 = (t >= 2) ? attn_vec(t, 2, q) : make_float4(0, 0, 0, 0);
    int4 xi = reinterpret_cast<const int4*>(input_x)[q];
    const float4* __restrict__ s1 = reinterpret_cast<const float4*>(g_states[1]);
    const float4* __restrict__ s2 = reinterpret_cast<const float4*>(g_states[2]);
    int e = u >> 3;
    float4 v = make_float4(xi.x == e ? a0.x : 0.0f, xi.y == e ? a0.y : 0.0f,
                           xi.z == e ? a0.z : 0.0f, xi.w == e ? a0.w : 0.0f);
    {
        float4 s = s1[u];
        v.x += a1.x * s.x; v.y += a1.y * s.y; v.z += a1.z * s.z; v.w += a1.w * s.w;
    }
    if (t >= 2) {
        float4 s = s2[u];
        v.x += a2.x * s.x; v.y += a2.y * s.y; v.z += a2.z * s.z; v.w += a2.w * s.w;
    }
    reinterpret_cast<float4*>(g_inp)[u] = v;
    int lane = threadIdx.x & 31;
    bool nzv = (v.x != 0.0f) | (v.y != 0.0f) | (v.z != 0.0f) | (v.w != 0.0f);
    unsigned m = __ballot_sync(0xffffffffu, nzv);
    if ((lane & 7) == 0) g_nz[e] = ((m >> ((lane >> 3) * 8)) & 0xffu) ? 1 : 0;
}

// ---------------- propagate: sparse-aware, fused batch sums ----------------
__global__ void k_prop(const int* __restrict__ heads, const int* __restrict__ tails,
                       const int* __restrict__ rels, int t, int nE) {
    const float4* __restrict__ x4 = reinterpret_cast<const float4*>(g_inp);
    float4* s4 = reinterpret_cast<float4*>(g_states[t + 1]);
    const float4* __restrict__ w4 = reinterpret_cast<const float4*>(g_wT[t]);
    int lane = threadIdx.x & 31;
    int q = lane & 7;
    int sub = lane >> 3;
    int warpId = (blockIdx.x * blockDim.x + threadIdx.x) >> 5;
    int nWarp = (gridDim.x * blockDim.x) >> 5;
    float4 acc = make_float4(0.0f, 0.0f, 0.0f, 0.0f);
    for (int e = warpId * 4 + sub; e < nE; e += nWarp * 4) {
        int h = heads[e], tl = tails[e];
        bool fh = g_nz[h] != 0, ft = g_nz[tl] != 0;
        if (fh | ft) {
            int r = rels[e];
            if (fh) {
                float4 xh = x4[h * 8 + q];
                if (xh.x != 0.0f || xh.y != 0.0f || xh.z != 0.0f || xh.w != 0.0f) {
                    float4 w1 = w4[r * 8 + q];
                    float4 m1 = make_float4(xh.x * w1.x, xh.y * w1.y,
                                            xh.z * w1.z, xh.w * w1.w);
                    red_add_v4(&s4[tl * 8 + q], m1);
                    acc.x += m1.x; acc.y += m1.y; acc.z += m1.z; acc.w += m1.w;
                }
            }
            if (ft) {
                float4 xt = x4[tl * 8 + q];
                if (xt.x != 0.0f || xt.y != 0.0f || xt.z != 0.0f || xt.w != 0.0f) {
                    float4 w2 = w4[(r + RSIZEc) * 8 + q];
                    float4 m2 = make_float4(xt.x * w2.x, xt.y * w2.y,
                                            xt.z * w2.z, xt.w * w2.w);
                    red_add_v4(&s4[h * 8 + q], m2);
                    acc.x += m2.x; acc.y += m2.y; acc.z += m2.z; acc.w += m2.w;
                }
            }
        }
    }
    acc.x += __shfl_xor_sync(0xffffffffu, acc.x, 8);
    acc.y += __shfl_xor_sync(0xffffffffu, acc.y, 8);
    acc.z += __shfl_xor_sync(0xffffffffu, acc.z, 8);
    acc.w += __shfl_xor_sync(0xffffffffu, acc.w, 8);
    acc.x += __shfl_xor_sync(0xffffffffu, acc.x, 16);
    acc.y += __shfl_xor_sync(0xffffffffu, acc.y, 16);
    acc.z += __shfl_xor_sync(0xffffffffu, acc.z, 16);
    acc.w += __shfl_xor_sync(0xffffffffu, acc.w, 16);
    __shared__ float sblk[Bsz];
    if (threadIdx.x < Bsz) sblk[threadIdx.x] = 0.0f;
    __syncthreads();
    if (lane < 8) {
        atomicAdd(&sblk[q * 4 + 0], acc.x);
        atomicAdd(&sblk[q * 4 + 1], acc.y);
        atomicAdd(&sblk[q * 4 + 2], acc.z);
        atomicAdd(&sblk[q * 4 + 3], acc.w);
    }
    __syncthreads();
    if (threadIdx.x < Bsz) atomicAdd(&g_sums[t][threadIdx.x], sblk[threadIdx.x]);
}

// ---------------- final combine, tiled transpose to (B, E) ------------------
__global__ void k_final(const int* __restrict__ input_x, float* __restrict__ out) {
    __shared__ float tile[32][33];
    int e0 = blockIdx.x * 32;
    int r = threadIdx.x >> 3, q = threadIdx.x & 7;
    float4 a0 = attn_vec(3, 0, q);
    float4 a1 = attn_vec(3, 1, q);
    float4 a2 = attn_vec(3, 2, q);
    float4 a3 = attn_vec(3, 3, q);
    int4 xi = reinterpret_cast<const int4*>(input_x)[q];
    const float4* __restrict__ s1 = reinterpret_cast<const float4*>(g_states[1]);
    const float4* __restrict__ s2 = reinterpret_cast<const float4*>(g_states[2]);
    const float4* __restrict__ s3 = reinterpret_cast<const float4*>(g_states[3]);
    int e = e0 + r;
    int u = e * 8 + q;
    float4 v1 = s1[u], v2 = s2[u], v3 = s3[u];
    float4 v;
    v.x = (xi.x == e ? a0.x : 0.0f) + a1.x * v1.x + a2.x * v2.x + a3.x * v3.x;
    v.y = (xi.y == e ? a0.y : 0.0f) + a1.y * v1.y + a2.y * v2.y + a3.y * v3.y;
    v.z = (xi.z == e ? a0.z : 0.0f) + a1.z * v1.z + a2.z * v2.z + a3.z * v3.z;
    v.w = (xi.w == e ? a0.w : 0.0f) + a1.w * v1.w + a2.w * v2.w + a3.w * v3.w;
    tile[r][4 * q + 0] = v.x;
    tile[r][4 * q + 1] = v.y;
    tile[r][4 * q + 2] = v.z;
    tile[r][4 * q + 3] = v.w;
    __syncthreads();
    int w = threadIdx.x >> 5, lane = threadIdx.x & 31;
#pragma unroll
    for (int bb = 0; bb < 4; bb++) {
        int b = w * 4 + bb;
        out[b * Ecnt + e0 + lane] = tile[lane][b];
    }
}

// ---------------- launch ----------------------------------------------------
extern "C" void kernel_launch(void* const* d_in, const int* in_sizes, int n_in,
                              void* d_out, int out_size) {
    const int* input_x = (const int*)d_in[0];
    const int* input_r = (const int*)d_in[1];
    const int* heads   = (const int*)d_in[2];
    const int* tails   = (const int*)d_in[3];
    const int* rels    = (const int*)d_in[4];
    const float* emb_W = (const float*)d_in[5];
    const float* W_ih  = (const float*)d_in[6];
    const float* W_hh  = (const float*)d_in[7];
    const float* b_ih  = (const float*)d_in[8];
    const float* b_hh  = (const float*)d_in[9];
    const float* lin_W = (const float*)d_in[10];
    const float* lin_b = (const float*)d_in[11];
    int nE = in_sizes[2];
    float* out = (float*)d_out;

    k_pre<<<1184, 256>>>(W_ih, W_hh, lin_W);
    k_seed<<<1, 32>>>(input_x);
    k_lstm4<<<32, 512>>>(emb_W, input_r, b_ih, b_hh);
    k_wsoft<<<97, 128>>>(lin_b);
    k_prop<<<1184, 256>>>(heads, tails, rels, 0, nE);
    for (int t = 1; t < 3; t++) {
        k_inp<<<1250, 256>>>(input_x, t);
        k_prop<<<1184, 256>>>(heads, tails, rels, t, nE);
    }
    k_final<<<1250, 256>>>(input_x, out);
}

// round 7
// speedup vs baseline: 2.5239x; 1.0933x over previous
#include <cuda_runtime.h>
#include <math.h>

#define Ecnt 40000
#define Bsz 32
#define Hd 128
#define NRELc 400
#define RSIZEc 200
#define TAU1 10.0f

// ---------------- scratch (static device memory; no allocs) ----------------
// state 0 is virtual (one-hot from input_x); states 1..3 are materialized.
__device__ float g_states[4][Ecnt * Bsz];   // [t][e*32+b]; index 0 unused
__device__ float g_inp[Ecnt * Bsz];         // att-combined input to propagate
__device__ unsigned char g_nz[Ecnt];        // per-entity nonzero flag for g_inp
__device__ float g_rnnT[4][Hd * Bsz];       // LSTM hidden, transposed [t][d*32+b]
__device__ float g_eatt[4][4][Bsz];         // softmaxed attention [t][tp][b]
__device__ float g_WihT[Hd * 4 * Hd];       // [d][k]
__device__ float g_WhhT[Hd * 4 * Hd];       // [d][k]
__device__ float g_wT[3][NRELc * Bsz];      // UNNORMALIZED exp weights [t][r*32+b]
__device__ float g_sums[3][Bsz];            // per-prop-step message sums

__device__ __forceinline__ float sigf(float x) { return 1.0f / (1.0f + expf(-x)); }

__device__ __forceinline__ void red_add_v4(float4* p, float4 v) {
    asm volatile("red.global.add.v4.f32 [%0], {%1, %2, %3, %4};"
                 :: "l"(p), "f"(v.x), "f"(v.y), "f"(v.z), "f"(v.w)
                 : "memory");
}

// ---------------- pre: zero states/nz/sums + weight transposes --------------
__global__ void k_pre(const float* __restrict__ W_ih,
                      const float* __restrict__ W_hh) {
    int i = blockIdx.x * blockDim.x + threadIdx.x;
    int stride = gridDim.x * blockDim.x;
    const float4 z = make_float4(0.0f, 0.0f, 0.0f, 0.0f);
    float4* s4 = reinterpret_cast<float4*>(g_states[1]);   // states 1..3 contiguous
    for (int j = i; j < 3 * Ecnt * 8; j += stride) s4[j] = z;
    for (int j = i; j < Ecnt / 4; j += stride) reinterpret_cast<int*>(g_nz)[j] = 0;
    if (i < 3 * Bsz) ((float*)g_sums)[i] = 0.0f;
    for (int j = i; j < 4 * Hd * Hd; j += stride) {
        int k = j / Hd, d = j % Hd;
        g_WihT[d * (4 * Hd) + k] = W_ih[j];
        g_WhhT[d * (4 * Hd) + k] = W_hh[j];
    }
}

// ---------------- seed t=0 prop input: zero 32 lines, set one-hot ----------
__global__ void k_seed(const int* __restrict__ input_x) {
    int w = threadIdx.x >> 5, lane = threadIdx.x & 31;
    int e = input_x[w];
    if (lane < 8)
        reinterpret_cast<float4*>(g_inp)[e * 8 + lane] =
            make_float4(0.0f, 0.0f, 0.0f, 0.0f);
    __syncthreads();
    if (threadIdx.x < Bsz) {
        int e2 = input_x[threadIdx.x];
        g_inp[e2 * Bsz + threadIdx.x] = 1.0f;
        g_nz[e2] = 1;
    }
}

// ------- LSTM: ih-pre + 4 steps + attention logits + attention softmax -----
__global__ void k_lstm4(const float* __restrict__ emb_W, const int* __restrict__ input_r,
                        const float* __restrict__ b_ih, const float* __restrict__ b_hh) {
    __shared__ float xs0[Hd];
    __shared__ float xs1[Hd];
    __shared__ float cs[Hd];
    __shared__ float gsh[4 * Hd];
    __shared__ float hist[4][Hd];
    __shared__ float attlg[4][4];
    int b = blockIdx.x, k = threadIdx.x;
    if (k < Hd) {
        xs0[k] = emb_W[input_r[b] * Hd + k];
        cs[k] = 0.0f;
        hist[3][k] = 0.0f;  // h seed for t=0 via hprev pointer below
    } else if (k < 2 * Hd) {
        xs1[k - Hd] = emb_W[NRELc * Hd + (k - Hd)];
    }
    __syncthreads();
    float bias = b_ih[k] + b_hh[k];
    float pre0 = bias, pre1 = bias;
#pragma unroll 8
    for (int d = 0; d < Hd; d++) {
        float w = g_WihT[d * (4 * Hd) + k];
        pre0 += xs0[d] * w;
        pre1 += xs1[d] * w;
    }
#pragma unroll
    for (int t = 0; t < 4; t++) {
        const float* hprev = (t == 0) ? hist[3] : hist[t - 1];
        float acc = (t < 3) ? pre0 : pre1;
#pragma unroll 8
        for (int d = 0; d < Hd; d++) acc += hprev[d] * g_WhhT[d * (4 * Hd) + k];
        gsh[k] = acc;
        __syncthreads();
        if (k < Hd) {
            float ig = gsh[k], fg = gsh[Hd + k], gg = gsh[2 * Hd + k], og = gsh[3 * Hd + k];
            float c = sigf(fg) * cs[k] + sigf(ig) * tanhf(gg);
            float h = sigf(og) * tanhf(c);
            cs[k] = c;
            hist[t][k] = h;
            g_rnnT[t][k * Bsz + b] = h;   // transposed for k_wexp
        }
        __syncthreads();
    }
    // attention logits: 16 warps, warp w = (t,tp)
    int w = k >> 5, lane = k & 31;
    int t = w >> 2, tp = w & 3;
    if (tp <= t) {
        float acc = 0.0f;
#pragma unroll
        for (int i = 0; i < 4; i++) {
            int d = lane + 32 * i;
            acc += hist[t][d] * hist[tp][d];
        }
#pragma unroll
        for (int s = 16; s > 0; s >>= 1) acc += __shfl_xor_sync(0xffffffffu, acc, s);
        if (lane == 0) attlg[t][tp] = acc;
    }
    __syncthreads();
    // attention softmax: thread k = t handles its row
    if (k < 4) {
        int tt = k;
        float m = -1e30f;
        for (int j = 0; j <= tt; j++) m = fmaxf(m, attlg[tt][j]);
        float s = 0.0f, e[4];
        for (int j = 0; j <= tt; j++) { e[j] = expf(attlg[tt][j] - m); s += e[j]; }
        float inv = 1.0f / s;
        for (int j = 0; j < 4; j++)
            g_eatt[tt][j][b] = (j <= tt) ? e[j] * inv : 0.0f;
    }
}

// ------ relation weights, UNNORMALIZED: w = exp(tau * (h·linW_r + b_r)) -----
// per-(t,b) softmax constants cancel through the s-normalization downstream.
// one warp per (t, r): lane = b. 1200 warps.
__global__ void k_wexp(const float* __restrict__ lin_W, const float* __restrict__ lin_b) {
    int wid = (blockIdx.x * blockDim.x + threadIdx.x) >> 5;
    int lane = threadIdx.x & 31;
    if (wid >= 3 * NRELc) return;
    int t = wid / NRELc;
    int r = wid - t * NRELc;
    const float* __restrict__ wr = lin_W + r * Hd;
    const float* __restrict__ hT = g_rnnT[t];
    float a0 = 0.0f, a1 = 0.0f, a2 = 0.0f, a3 = 0.0f;
#pragma unroll
    for (int d = 0; d < Hd; d += 4) {
        a0 += wr[d + 0] * hT[(d + 0) * Bsz + lane];
        a1 += wr[d + 1] * hT[(d + 1) * Bsz + lane];
        a2 += wr[d + 2] * hT[(d + 2) * Bsz + lane];
        a3 += wr[d + 3] * hT[(d + 3) * Bsz + lane];
    }
    float l = ((a0 + a1) + (a2 + a3) + lin_b[r]) * TAU1;
    g_wT[t][r * Bsz + lane] = expf(l);
}

// norm for state j (j>=1) = 1/max(g_sums[j-1][b], 1e-7); state 0 norm = 1
__device__ __forceinline__ float4 attn_vec(int t, int j, int q) {
    float4 e = reinterpret_cast<const float4*>(g_eatt)[(t * 4 + j) * 8 + q];
    if (j >= 1) {
        float4 s = reinterpret_cast<const float4*>(g_sums)[(j - 1) * 8 + q];
        e.x *= 1.0f / fmaxf(s.x, 1e-7f);
        e.y *= 1.0f / fmaxf(s.y, 1e-7f);
        e.z *= 1.0f / fmaxf(s.z, 1e-7f);
        e.w *= 1.0f / fmaxf(s.w, 1e-7f);
    }
    return e;
}

// ---------------- combine states -> g_inp + nz flags (t = 1 or 2) ----------
__global__ void k_inp(const int* __restrict__ input_x, int t) {
    int u = blockIdx.x * blockDim.x + threadIdx.x;
    int q = u & 7;
    float4 a0 = attn_vec(t, 0, q);
    float4 a1 = attn_vec(t, 1, q);
    float4 a2 = (t >= 2) ? attn_vec(t, 2, q) : make_float4(0, 0, 0, 0);
    int4 xi = reinterpret_cast<const int4*>(input_x)[q];
    const float4* __restrict__ s1 = reinterpret_cast<const float4*>(g_states[1]);
    const float4* __restrict__ s2 = reinterpret_cast<const float4*>(g_states[2]);
    int e = u >> 3;
    float4 v = make_float4(xi.x == e ? a0.x : 0.0f, xi.y == e ? a0.y : 0.0f,
                           xi.z == e ? a0.z : 0.0f, xi.w == e ? a0.w : 0.0f);
    {
        float4 s = s1[u];
        v.x += a1.x * s.x; v.y += a1.y * s.y; v.z += a1.z * s.z; v.w += a1.w * s.w;
    }
    if (t >= 2) {
        float4 s = s2[u];
        v.x += a2.x * s.x; v.y += a2.y * s.y; v.z += a2.z * s.z; v.w += a2.w * s.w;
    }
    reinterpret_cast<float4*>(g_inp)[u] = v;
    int lane = threadIdx.x & 31;
    bool nzv = (v.x != 0.0f) | (v.y != 0.0f) | (v.z != 0.0f) | (v.w != 0.0f);
    unsigned m = __ballot_sync(0xffffffffu, nzv);
    if ((lane & 7) == 0) g_nz[e] = ((m >> ((lane >> 3) * 8)) & 0xffu) ? 1 : 0;
}

// ---------------- propagate: sparse-aware, fused batch sums ----------------
__global__ void k_prop(const int* __restrict__ heads, const int* __restrict__ tails,
                       const int* __restrict__ rels, int t, int nE) {
    const float4* __restrict__ x4 = reinterpret_cast<const float4*>(g_inp);
    float4* s4 = reinterpret_cast<float4*>(g_states[t + 1]);
    const float4* __restrict__ w4 = reinterpret_cast<const float4*>(g_wT[t]);
    int lane = threadIdx.x & 31;
    int q = lane & 7;
    int sub = lane >> 3;
    int warpId = (blockIdx.x * blockDim.x + threadIdx.x) >> 5;
    int nWarp = (gridDim.x * blockDim.x) >> 5;
    float4 acc = make_float4(0.0f, 0.0f, 0.0f, 0.0f);
    for (int e = warpId * 4 + sub; e < nE; e += nWarp * 4) {
        int h = heads[e], tl = tails[e];
        bool fh = g_nz[h] != 0, ft = g_nz[tl] != 0;
        if (fh | ft) {
            int r = rels[e];
            if (fh) {
                float4 xh = x4[h * 8 + q];
                if (xh.x != 0.0f || xh.y != 0.0f || xh.z != 0.0f || xh.w != 0.0f) {
                    float4 w1 = w4[r * 8 + q];
                    float4 m1 = make_float4(xh.x * w1.x, xh.y * w1.y,
                                            xh.z * w1.z, xh.w * w1.w);
                    red_add_v4(&s4[tl * 8 + q], m1);
                    acc.x += m1.x; acc.y += m1.y; acc.z += m1.z; acc.w += m1.w;
                }
            }
            if (ft) {
                float4 xt = x4[tl * 8 + q];
                if (xt.x != 0.0f || xt.y != 0.0f || xt.z != 0.0f || xt.w != 0.0f) {
                    float4 w2 = w4[(r + RSIZEc) * 8 + q];
                    float4 m2 = make_float4(xt.x * w2.x, xt.y * w2.y,
                                            xt.z * w2.z, xt.w * w2.w);
                    red_add_v4(&s4[h * 8 + q], m2);
                    acc.x += m2.x; acc.y += m2.y; acc.z += m2.z; acc.w += m2.w;
                }
            }
        }
    }
    acc.x += __shfl_xor_sync(0xffffffffu, acc.x, 8);
    acc.y += __shfl_xor_sync(0xffffffffu, acc.y, 8);
    acc.z += __shfl_xor_sync(0xffffffffu, acc.z, 8);
    acc.w += __shfl_xor_sync(0xffffffffu, acc.w, 8);
    acc.x += __shfl_xor_sync(0xffffffffu, acc.x, 16);
    acc.y += __shfl_xor_sync(0xffffffffu, acc.y, 16);
    acc.z += __shfl_xor_sync(0xffffffffu, acc.z, 16);
    acc.w += __shfl_xor_sync(0xffffffffu, acc.w, 16);
    __shared__ float sblk[Bsz];
    if (threadIdx.x < Bsz) sblk[threadIdx.x] = 0.0f;
    __syncthreads();
    if (lane < 8) {
        atomicAdd(&sblk[q * 4 + 0], acc.x);
        atomicAdd(&sblk[q * 4 + 1], acc.y);
        atomicAdd(&sblk[q * 4 + 2], acc.z);
        atomicAdd(&sblk[q * 4 + 3], acc.w);
    }
    __syncthreads();
    if (threadIdx.x < Bsz) atomicAdd(&g_sums[t][threadIdx.x], sblk[threadIdx.x]);
}

// ---------------- final combine, tiled transpose to (B, E) ------------------
__global__ void k_final(const int* __restrict__ input_x, float* __restrict__ out) {
    __shared__ float tile[32][33];
    int e0 = blockIdx.x * 32;
    int r = threadIdx.x >> 3, q = threadIdx.x & 7;
    float4 a0 = attn_vec(3, 0, q);
    float4 a1 = attn_vec(3, 1, q);
    float4 a2 = attn_vec(3, 2, q);
    float4 a3 = attn_vec(3, 3, q);
    int4 xi = reinterpret_cast<const int4*>(input_x)[q];
    const float4* __restrict__ s1 = reinterpret_cast<const float4*>(g_states[1]);
    const float4* __restrict__ s2 = reinterpret_cast<const float4*>(g_states[2]);
    const float4* __restrict__ s3 = reinterpret_cast<const float4*>(g_states[3]);
    int e = e0 + r;
    int u = e * 8 + q;
    float4 v1 = s1[u], v2 = s2[u], v3 = s3[u];
    float4 v;
    v.x = (xi.x == e ? a0.x : 0.0f) + a1.x * v1.x + a2.x * v2.x + a3.x * v3.x;
    v.y = (xi.y == e ? a0.y : 0.0f) + a1.y * v1.y + a2.y * v2.y + a3.y * v3.y;
    v.z = (xi.z == e ? a0.z : 0.0f) + a1.z * v1.z + a2.z * v2.z + a3.z * v3.z;
    v.w = (xi.w == e ? a0.w : 0.0f) + a1.w * v1.w + a2.w * v2.w + a3.w * v3.w;
    tile[r][4 * q + 0] = v.x;
    tile[r][4 * q + 1] = v.y;
    tile[r][4 * q + 2] = v.z;
    tile[r][4 * q + 3] = v.w;
    __syncthreads();
    int w = threadIdx.x >> 5, lane = threadIdx.x & 31;
#pragma unroll
    for (int bb = 0; bb < 4; bb++) {
        int b = w * 4 + bb;
        out[b * Ecnt + e0 + lane] = tile[lane][b];
    }
}

// ---------------- launch ----------------------------------------------------
extern "C" void kernel_launch(void* const* d_in, const int* in_sizes, int n_in,
                              void* d_out, int out_size) {
    const int* input_x = (const int*)d_in[0];
    const int* input_r = (const int*)d_in[1];
    const int* heads   = (const int*)d_in[2];
    const int* tails   = (const int*)d_in[3];
    const int* rels    = (const int*)d_in[4];
    const float* emb_W = (const float*)d_in[5];
    const float* W_ih  = (const float*)d_in[6];
    const float* W_hh  = (const float*)d_in[7];
    const float* b_ih  = (const float*)d_in[8];
    const float* b_hh  = (const float*)d_in[9];
    const float* lin_W = (const float*)d_in[10];
    const float* lin_b = (const float*)d_in[11];
    int nE = in_sizes[2];
    float* out = (float*)d_out;

    k_pre<<<1184, 256>>>(W_ih, W_hh);
    k_seed<<<1, 1024>>>(input_x);
    k_lstm4<<<32, 512>>>(emb_W, input_r, b_ih, b_hh);
    k_wexp<<<300, 128>>>(lin_W, lin_b);
    k_prop<<<1184, 256>>>(heads, tails, rels, 0, nE);
    for (int t = 1; t < 3; t++) {
        k_inp<<<1250, 256>>>(input_x, t);
        k_prop<<<1184, 256>>>(heads, tails, rels, t, nE);
    }
    k_final<<<1250, 256>>>(input_x, out);
}

// round 8
// speedup vs baseline: 2.6222x; 1.0389x over previous
#include <cuda_runtime.h>
#include <math.h>

#define Ecnt 40000
#define Bsz 32
#define Hd 128
#define NRELc 400
#define RSIZEc 200
#define TAU1 10.0f

// ---------------- scratch (static device memory; no allocs) ----------------
// state 0 is virtual (one-hot from input_x); states 1..3 are materialized.
__device__ float g_states[4][Ecnt * Bsz];   // [t][e*32+b]; index 0 unused
__device__ float g_inp[Ecnt * Bsz];         // att-combined input to propagate
__device__ unsigned char g_nz[Ecnt];        // per-entity nonzero flag for g_inp
__device__ float g_rnnT[4][Hd * Bsz];       // LSTM hidden, transposed [t][d*32+b]
__device__ float g_eatt[4][4][Bsz];         // softmaxed attention [t][tp][b]
__device__ float g_WihT[Hd * 4 * Hd];       // [d][k]
__device__ float g_WhhT[Hd * 4 * Hd];       // [d][k]
__device__ float g_wT[3][NRELc * Bsz];      // UNNORMALIZED exp weights [t][r*32+b]
__device__ float g_sums[3][Bsz];            // per-prop-step message sums

__device__ __forceinline__ float sigf(float x) { return 1.0f / (1.0f + expf(-x)); }

__device__ __forceinline__ void red_add_v4(float4* p, float4 v) {
    asm volatile("red.global.add.v4.f32 [%0], {%1, %2, %3, %4};"
                 :: "l"(p), "f"(v.x), "f"(v.y), "f"(v.z), "f"(v.w)
                 : "memory");
}

// ---------------- pre: zero states/nz/sums + weight transposes --------------
__global__ void k_pre(const float* __restrict__ W_ih,
                      const float* __restrict__ W_hh) {
    int i = blockIdx.x * blockDim.x + threadIdx.x;
    int stride = gridDim.x * blockDim.x;
    const float4 z = make_float4(0.0f, 0.0f, 0.0f, 0.0f);
    float4* s4 = reinterpret_cast<float4*>(g_states[1]);   // states 1..3 contiguous
    for (int j = i; j < 3 * Ecnt * 8; j += stride) s4[j] = z;
    for (int j = i; j < Ecnt / 4; j += stride) reinterpret_cast<int*>(g_nz)[j] = 0;
    if (i < 3 * Bsz) ((float*)g_sums)[i] = 0.0f;
    for (int j = i; j < 4 * Hd * Hd; j += stride) {
        int k = j / Hd, d = j % Hd;
        g_WihT[d * (4 * Hd) + k] = W_ih[j];
        g_WhhT[d * (4 * Hd) + k] = W_hh[j];
    }
}

// ---------------- seed t=0 prop input: zero 32 lines, set one-hot ----------
__global__ void k_seed(const int* __restrict__ input_x) {
    int w = threadIdx.x >> 5, lane = threadIdx.x & 31;
    int e = input_x[w];
    if (lane < 8)
        reinterpret_cast<float4*>(g_inp)[e * 8 + lane] =
            make_float4(0.0f, 0.0f, 0.0f, 0.0f);
    __syncthreads();
    if (threadIdx.x < Bsz) {
        int e2 = input_x[threadIdx.x];
        g_inp[e2 * Bsz + threadIdx.x] = 1.0f;
        g_nz[e2] = 1;
    }
}

// ------- LSTM: ih-pre + 4 steps + attention logits + attention softmax -----
__global__ void k_lstm4(const float* __restrict__ emb_W, const int* __restrict__ input_r,
                        const float* __restrict__ b_ih, const float* __restrict__ b_hh) {
    __shared__ float xs0[Hd];
    __shared__ float xs1[Hd];
    __shared__ float cs[Hd];
    __shared__ float gsh[4 * Hd];
    __shared__ float hist[4][Hd];
    __shared__ float attlg[4][4];
    int b = blockIdx.x, k = threadIdx.x;
    if (k < Hd) {
        xs0[k] = emb_W[input_r[b] * Hd + k];
        cs[k] = 0.0f;
        hist[3][k] = 0.0f;  // h seed for t=0 via hprev pointer below
    } else if (k < 2 * Hd) {
        xs1[k - Hd] = emb_W[NRELc * Hd + (k - Hd)];
    }
    __syncthreads();
    float bias = b_ih[k] + b_hh[k];
    float pre0 = bias, pre1 = bias;
#pragma unroll 8
    for (int d = 0; d < Hd; d++) {
        float w = g_WihT[d * (4 * Hd) + k];
        pre0 += xs0[d] * w;
        pre1 += xs1[d] * w;
    }
#pragma unroll
    for (int t = 0; t < 4; t++) {
        const float* hprev = (t == 0) ? hist[3] : hist[t - 1];
        float acc = (t < 3) ? pre0 : pre1;
#pragma unroll 8
        for (int d = 0; d < Hd; d++) acc += hprev[d] * g_WhhT[d * (4 * Hd) + k];
        gsh[k] = acc;
        __syncthreads();
        if (k < Hd) {
            float ig = gsh[k], fg = gsh[Hd + k], gg = gsh[2 * Hd + k], og = gsh[3 * Hd + k];
            float c = sigf(fg) * cs[k] + sigf(ig) * tanhf(gg);
            float h = sigf(og) * tanhf(c);
            cs[k] = c;
            hist[t][k] = h;
            g_rnnT[t][k * Bsz + b] = h;   // transposed for k_wexp
        }
        __syncthreads();
    }
    // attention logits: 16 warps, warp w = (t,tp)
    int w = k >> 5, lane = k & 31;
    int t = w >> 2, tp = w & 3;
    if (tp <= t) {
        float acc = 0.0f;
#pragma unroll
        for (int i = 0; i < 4; i++) {
            int d = lane + 32 * i;
            acc += hist[t][d] * hist[tp][d];
        }
#pragma unroll
        for (int s = 16; s > 0; s >>= 1) acc += __shfl_xor_sync(0xffffffffu, acc, s);
        if (lane == 0) attlg[t][tp] = acc;
    }
    __syncthreads();
    // attention softmax: thread k = t handles its row
    if (k < 4) {
        int tt = k;
        float m = -1e30f;
        for (int j = 0; j <= tt; j++) m = fmaxf(m, attlg[tt][j]);
        float s = 0.0f, e[4];
        for (int j = 0; j <= tt; j++) { e[j] = expf(attlg[tt][j] - m); s += e[j]; }
        float inv = 1.0f / s;
        for (int j = 0; j < 4; j++)
            g_eatt[tt][j][b] = (j <= tt) ? e[j] * inv : 0.0f;
    }
}

// ------ relation weights, UNNORMALIZED: w = exp(tau * (h·linW_r + b_r)) -----
// per-(t,b) softmax constants cancel through the s-normalization downstream.
// one warp per (t, r): lane = b. 1200 warps.
__global__ void k_wexp(const float* __restrict__ lin_W, const float* __restrict__ lin_b) {
    int wid = (blockIdx.x * blockDim.x + threadIdx.x) >> 5;
    int lane = threadIdx.x & 31;
    if (wid >= 3 * NRELc) return;
    int t = wid / NRELc;
    int r = wid - t * NRELc;
    const float* __restrict__ wr = lin_W + r * Hd;
    const float* __restrict__ hT = g_rnnT[t];
    float a0 = 0.0f, a1 = 0.0f, a2 = 0.0f, a3 = 0.0f;
#pragma unroll
    for (int d = 0; d < Hd; d += 4) {
        a0 += wr[d + 0] * hT[(d + 0) * Bsz + lane];
        a1 += wr[d + 1] * hT[(d + 1) * Bsz + lane];
        a2 += wr[d + 2] * hT[(d + 2) * Bsz + lane];
        a3 += wr[d + 3] * hT[(d + 3) * Bsz + lane];
    }
    float l = ((a0 + a1) + (a2 + a3) + lin_b[r]) * TAU1;
    g_wT[t][r * Bsz + lane] = expf(l);
}

// norm for state j (j>=1) = 1/max(g_sums[j-1][b], 1e-7); state 0 norm = 1
__device__ __forceinline__ float4 attn_vec(int t, int j, int q) {
    float4 e = reinterpret_cast<const float4*>(g_eatt)[(t * 4 + j) * 8 + q];
    if (j >= 1) {
        float4 s = reinterpret_cast<const float4*>(g_sums)[(j - 1) * 8 + q];
        e.x *= 1.0f / fmaxf(s.x, 1e-7f);
        e.y *= 1.0f / fmaxf(s.y, 1e-7f);
        e.z *= 1.0f / fmaxf(s.z, 1e-7f);
        e.w *= 1.0f / fmaxf(s.w, 1e-7f);
    }
    return e;
}

// ---------------- combine states -> g_inp + nz flags (t = 1 or 2) ----------
__global__ void k_inp(const int* __restrict__ input_x, int t) {
    int u = blockIdx.x * blockDim.x + threadIdx.x;
    int q = u & 7;
    float4 a0 = attn_vec(t, 0, q);
    float4 a1 = attn_vec(t, 1, q);
    float4 a2 = (t >= 2) ? attn_vec(t, 2, q) : make_float4(0, 0, 0, 0);
    int4 xi = reinterpret_cast<const int4*>(input_x)[q];
    const float4* __restrict__ s1 = reinterpret_cast<const float4*>(g_states[1]);
    const float4* __restrict__ s2 = reinterpret_cast<const float4*>(g_states[2]);
    int e = u >> 3;
    float4 v = make_float4(xi.x == e ? a0.x : 0.0f, xi.y == e ? a0.y : 0.0f,
                           xi.z == e ? a0.z : 0.0f, xi.w == e ? a0.w : 0.0f);
    {
        float4 s = s1[u];
        v.x += a1.x * s.x; v.y += a1.y * s.y; v.z += a1.z * s.z; v.w += a1.w * s.w;
    }
    if (t >= 2) {
        float4 s = s2[u];
        v.x += a2.x * s.x; v.y += a2.y * s.y; v.z += a2.z * s.z; v.w += a2.w * s.w;
    }
    reinterpret_cast<float4*>(g_inp)[u] = v;
    int lane = threadIdx.x & 31;
    bool nzv = (v.x != 0.0f) | (v.y != 0.0f) | (v.z != 0.0f) | (v.w != 0.0f);
    unsigned m = __ballot_sync(0xffffffffu, nzv);
    if ((lane & 7) == 0) g_nz[e] = ((m >> ((lane >> 3) * 8)) & 0xffu) ? 1 : 0;
}

// ---------------- propagate: sparse-aware, fused batch sums ----------------
__global__ void k_prop(const int* __restrict__ heads, const int* __restrict__ tails,
                       const int* __restrict__ rels, int t, int nE) {
    const float4* __restrict__ x4 = reinterpret_cast<const float4*>(g_inp);
    float4* s4 = reinterpret_cast<float4*>(g_states[t + 1]);
    const float4* __restrict__ w4 = reinterpret_cast<const float4*>(g_wT[t]);
    int lane = threadIdx.x & 31;
    int q = lane & 7;
    int sub = lane >> 3;
    int warpId = (blockIdx.x * blockDim.x + threadIdx.x) >> 5;
    int nWarp = (gridDim.x * blockDim.x) >> 5;
    float4 acc = make_float4(0.0f, 0.0f, 0.0f, 0.0f);
    for (int e = warpId * 4 + sub; e < nE; e += nWarp * 4) {
        int h = heads[e], tl = tails[e];
        bool fh = g_nz[h] != 0, ft = g_nz[tl] != 0;
        if (fh | ft) {
            int r = rels[e];
            if (fh) {
                float4 xh = x4[h * 8 + q];
                if (xh.x != 0.0f || xh.y != 0.0f || xh.z != 0.0f || xh.w != 0.0f) {
                    float4 w1 = w4[r * 8 + q];
                    float4 m1 = make_float4(xh.x * w1.x, xh.y * w1.y,
                                            xh.z * w1.z, xh.w * w1.w);
                    red_add_v4(&s4[tl * 8 + q], m1);
                    acc.x += m1.x; acc.y += m1.y; acc.z += m1.z; acc.w += m1.w;
                }
            }
            if (ft) {
                float4 xt = x4[tl * 8 + q];
                if (xt.x != 0.0f || xt.y != 0.0f || xt.z != 0.0f || xt.w != 0.0f) {
                    float4 w2 = w4[(r + RSIZEc) * 8 + q];
                    float4 m2 = make_float4(xt.x * w2.x, xt.y * w2.y,
                                            xt.z * w2.z, xt.w * w2.w);
                    red_add_v4(&s4[h * 8 + q], m2);
                    acc.x += m2.x; acc.y += m2.y; acc.z += m2.z; acc.w += m2.w;
                }
            }
        }
    }
    acc.x += __shfl_xor_sync(0xffffffffu, acc.x, 8);
    acc.y += __shfl_xor_sync(0xffffffffu, acc.y, 8);
    acc.z += __shfl_xor_sync(0xffffffffu, acc.z, 8);
    acc.w += __shfl_xor_sync(0xffffffffu, acc.w, 8);
    acc.x += __shfl_xor_sync(0xffffffffu, acc.x, 16);
    acc.y += __shfl_xor_sync(0xffffffffu, acc.y, 16);
    acc.z += __shfl_xor_sync(0xffffffffu, acc.z, 16);
    acc.w += __shfl_xor_sync(0xffffffffu, acc.w, 16);
    __shared__ float sblk[Bsz];
    if (threadIdx.x < Bsz) sblk[threadIdx.x] = 0.0f;
    __syncthreads();
    if (lane < 8) {
        atomicAdd(&sblk[q * 4 + 0], acc.x);
        atomicAdd(&sblk[q * 4 + 1], acc.y);
        atomicAdd(&sblk[q * 4 + 2], acc.z);
        atomicAdd(&sblk[q * 4 + 3], acc.w);
    }
    __syncthreads();
    if (threadIdx.x < Bsz) atomicAdd(&g_sums[t][threadIdx.x], sblk[threadIdx.x]);
}

// ---------------- final combine, tiled transpose to (B, E) ------------------
__global__ void k_final(const int* __restrict__ input_x, float* __restrict__ out) {
    __shared__ float tile[32][33];
    int e0 = blockIdx.x * 32;
    int r = threadIdx.x >> 3, q = threadIdx.x & 7;
    float4 a0 = attn_vec(3, 0, q);
    float4 a1 = attn_vec(3, 1, q);
    float4 a2 = attn_vec(3, 2, q);
    float4 a3 = attn_vec(3, 3, q);
    int4 xi = reinterpret_cast<const int4*>(input_x)[q];
    const float4* __restrict__ s1 = reinterpret_cast<const float4*>(g_states[1]);
    const float4* __restrict__ s2 = reinterpret_cast<const float4*>(g_states[2]);
    const float4* __restrict__ s3 = reinterpret_cast<const float4*>(g_states[3]);
    int e = e0 + r;
    int u = e * 8 + q;
    float4 v1 = s1[u], v2 = s2[u], v3 = s3[u];
    float4 v;
    v.x = (xi.x == e ? a0.x : 0.0f) + a1.x * v1.x + a2.x * v2.x + a3.x * v3.x;
    v.y = (xi.y == e ? a0.y : 0.0f) + a1.y * v1.y + a2.y * v2.y + a3.y * v3.y;
    v.z = (xi.z == e ? a0.z : 0.0f) + a1.z * v1.z + a2.z * v2.z + a3.z * v3.z;
    v.w = (xi.w == e ? a0.w : 0.0f) + a1.w * v1.w + a2.w * v2.w + a3.w * v3.w;
    tile[r][4 * q + 0] = v.x;
    tile[r][4 * q + 1] = v.y;
    tile[r][4 * q + 2] = v.z;
    tile[r][4 * q + 3] = v.w;
    __syncthreads();
    int w = threadIdx.x >> 5, lane = threadIdx.x & 31;
#pragma unroll
    for (int bb = 0; bb < 4; bb++) {
        int b = w * 4 + bb;
        out[b * Ecnt + e0 + lane] = tile[lane][b];
    }
}

// ---------------- launch ----------------------------------------------------
extern "C" void kernel_launch(void* const* d_in, const int* in_sizes, int n_in,
                              void* d_out, int out_size) {
    const int* input_x = (const int*)d_in[0];
    const int* input_r = (const int*)d_in[1];
    const int* heads   = (const int*)d_in[2];
    const int* tails   = (const int*)d_in[3];
    const int* rels    = (const int*)d_in[4];
    const float* emb_W = (const float*)d_in[5];
    const float* W_ih  = (const float*)d_in[6];
    const float* W_hh  = (const float*)d_in[7];
    const float* b_ih  = (const float*)d_in[8];
    const float* b_hh  = (const float*)d_in[9];
    const float* lin_W = (const float*)d_in[10];
    const float* lin_b = (const float*)d_in[11];
    int nE = in_sizes[2];
    float* out = (float*)d_out;

    k_pre<<<1184, 256>>>(W_ih, W_hh);
    k_seed<<<1, 1024>>>(input_x);
    k_lstm4<<<32, 512>>>(emb_W, input_r, b_ih, b_hh);
    k_wexp<<<300, 128>>>(lin_W, lin_b);
    k_prop<<<1184, 256>>>(heads, tails, rels, 0, nE);
    for (int t = 1; t < 3; t++) {
        k_inp<<<1250, 256>>>(input_x, t);
        k_prop<<<1184, 256>>>(heads, tails, rels, t, nE);
    }
    k_final<<<1250, 256>>>(input_x, out);
}

// round 9
// speedup vs baseline: 2.7292x; 1.0408x over previous
#include <cuda_runtime.h>
#include <math.h>

#define Ecnt 40000
#define Bsz 32
#define Hd 128
#define NRELc 400
#define RSIZEc 200
#define TAU1 10.0f

// ---------------- scratch (static device memory; no allocs) ----------------
// state 0 is virtual (one-hot from input_x); states 1..3 are materialized.
__device__ float g_states[4][Ecnt * Bsz];   // [t][e*32+b]; index 0 unused
__device__ float g_inp[Ecnt * Bsz];         // att-combined input to propagate
__device__ unsigned char g_nz[Ecnt];        // per-entity nonzero flag for g_inp
__device__ float g_rnnT[4][Hd * Bsz];       // LSTM hidden, transposed [t][d*32+b]
__device__ float g_eatt[4][4][Bsz];         // softmaxed attention [t][tp][b]
__device__ float g_WihT[Hd * 4 * Hd];       // [d][k]
__device__ float g_WhhT[Hd * 4 * Hd];       // [d][k]
__device__ float g_wT[3][NRELc * Bsz];      // UNNORMALIZED exp weights [t][r*32+b]
__device__ float g_sums[3][Bsz];            // per-prop-step message sums

__device__ __forceinline__ float sigf(float x) { return 1.0f / (1.0f + expf(-x)); }

__device__ __forceinline__ void red_add_v4(float4* p, float4 v) {
    asm volatile("red.global.add.v4.f32 [%0], {%1, %2, %3, %4};"
                 :: "l"(p), "f"(v.x), "f"(v.y), "f"(v.z), "f"(v.w)
                 : "memory");
}

// ---------------- pre: zero states/nz/sums ----------------
__global__ void k_pre() {
    int i = blockIdx.x * blockDim.x + threadIdx.x;
    int stride = gridDim.x * blockDim.x;
    const float4 z = make_float4(0.0f, 0.0f, 0.0f, 0.0f);
    float4* s4 = reinterpret_cast<float4*>(g_states[1]);   // states 1..3 contiguous
    for (int j = i; j < 3 * Ecnt * 8; j += stride) s4[j] = z;
    for (int j = i; j < Ecnt / 4; j += stride) reinterpret_cast<int*>(g_nz)[j] = 0;
    if (i < 3 * Bsz) ((float*)g_sums)[i] = 0.0f;
}

// ---------------- tiled transposes of W_ih / W_hh (coalesced both ways) ----
// W is [4H=512][H=128]; WT is [128][512]. 32x32 tiles: 64 tiles per matrix.
__global__ void k_trans(const float* __restrict__ W_ih,
                        const float* __restrict__ W_hh) {
    __shared__ float tile[32][33];
    int m = blockIdx.x >> 6;           // 0: ih, 1: hh
    int bid = blockIdx.x & 63;
    int kb = (bid >> 2) * 32;          // k-tile base (16 tiles along k)
    int db = (bid & 3) * 32;           // d-tile base (4 tiles along d)
    const float* __restrict__ W = m ? W_hh : W_ih;
    float* WT = m ? g_WhhT : g_WihT;
    int tx = threadIdx.x & 31, ty0 = threadIdx.x >> 5;   // 32x8
#pragma unroll
    for (int i = 0; i < 4; i++) {
        int ty = ty0 + 8 * i;
        tile[ty][tx] = W[(kb + ty) * Hd + db + tx];
    }
    __syncthreads();
#pragma unroll
    for (int i = 0; i < 4; i++) {
        int ty = ty0 + 8 * i;
        WT[(db + ty) * (4 * Hd) + kb + tx] = tile[tx][ty];
    }
}

// ---------------- seed t=0 prop input: zero 32 lines, set one-hot ----------
__global__ void k_seed(const int* __restrict__ input_x) {
    int w = threadIdx.x >> 5, lane = threadIdx.x & 31;
    int e = input_x[w];
    if (lane < 8)
        reinterpret_cast<float4*>(g_inp)[e * 8 + lane] =
            make_float4(0.0f, 0.0f, 0.0f, 0.0f);
    __syncthreads();
    if (threadIdx.x < Bsz) {
        int e2 = input_x[threadIdx.x];
        g_inp[e2 * Bsz + threadIdx.x] = 1.0f;
        g_nz[e2] = 1;
    }
}

// ------- LSTM: ih-pre + 4 steps + attention logits + attention softmax -----
__global__ void k_lstm4(const float* __restrict__ emb_W, const int* __restrict__ input_r,
                        const float* __restrict__ b_ih, const float* __restrict__ b_hh) {
    __shared__ float xs0[Hd];
    __shared__ float xs1[Hd];
    __shared__ float cs[Hd];
    __shared__ float gsh[4 * Hd];
    __shared__ float hist[4][Hd];
    __shared__ float attlg[4][4];
    int b = blockIdx.x, k = threadIdx.x;
    if (k < Hd) {
        xs0[k] = emb_W[input_r[b] * Hd + k];
        cs[k] = 0.0f;
        hist[3][k] = 0.0f;  // h seed for t=0 via hprev pointer below
    } else if (k < 2 * Hd) {
        xs1[k - Hd] = emb_W[NRELc * Hd + (k - Hd)];
    }
    __syncthreads();
    float bias = b_ih[k] + b_hh[k];
    float pre0 = bias, pre1 = bias;
#pragma unroll 8
    for (int d = 0; d < Hd; d++) {
        float w = g_WihT[d * (4 * Hd) + k];
        pre0 += xs0[d] * w;
        pre1 += xs1[d] * w;
    }
#pragma unroll
    for (int t = 0; t < 4; t++) {
        const float* hprev = (t == 0) ? hist[3] : hist[t - 1];
        float acc = (t < 3) ? pre0 : pre1;
#pragma unroll 8
        for (int d = 0; d < Hd; d++) acc += hprev[d] * g_WhhT[d * (4 * Hd) + k];
        gsh[k] = acc;
        __syncthreads();
        if (k < Hd) {
            float ig = gsh[k], fg = gsh[Hd + k], gg = gsh[2 * Hd + k], og = gsh[3 * Hd + k];
            float c = sigf(fg) * cs[k] + sigf(ig) * tanhf(gg);
            float h = sigf(og) * tanhf(c);
            cs[k] = c;
            hist[t][k] = h;
            g_rnnT[t][k * Bsz + b] = h;   // transposed for k_wexp
        }
        __syncthreads();
    }
    // attention logits: 16 warps, warp w = (t,tp)
    int w = k >> 5, lane = k & 31;
    int t = w >> 2, tp = w & 3;
    if (tp <= t) {
        float acc = 0.0f;
#pragma unroll
        for (int i = 0; i < 4; i++) {
            int d = lane + 32 * i;
            acc += hist[t][d] * hist[tp][d];
        }
#pragma unroll
        for (int s = 16; s > 0; s >>= 1) acc += __shfl_xor_sync(0xffffffffu, acc, s);
        if (lane == 0) attlg[t][tp] = acc;
    }
    __syncthreads();
    // attention softmax: thread k = t handles its row
    if (k < 4) {
        int tt = k;
        float m = -1e30f;
        for (int j = 0; j <= tt; j++) m = fmaxf(m, attlg[tt][j]);
        float s = 0.0f, e[4];
        for (int j = 0; j <= tt; j++) { e[j] = expf(attlg[tt][j] - m); s += e[j]; }
        float inv = 1.0f / s;
        for (int j = 0; j < 4; j++)
            g_eatt[tt][j][b] = (j <= tt) ? e[j] * inv : 0.0f;
    }
}

// ------ relation weights, UNNORMALIZED: w = exp(tau * (h·linW_r + b_r)) -----
// per-(t,b) softmax constants cancel through the s-normalization downstream.
// one warp per (t, r): lane = b. Weight row staged via ONE float4/lane +
// shuffle broadcast (replaces 128 serial scalar LDGs).
__global__ void k_wexp(const float* __restrict__ lin_W, const float* __restrict__ lin_b) {
    int wid = (blockIdx.x * blockDim.x + threadIdx.x) >> 5;
    int lane = threadIdx.x & 31;
    if (wid >= 3 * NRELc) return;
    int t = wid / NRELc;
    int r = wid - t * NRELc;
    float4 wv = reinterpret_cast<const float4*>(lin_W + r * Hd)[lane];
    const float* __restrict__ hT = g_rnnT[t];
    float a0 = 0.0f, a1 = 0.0f, a2 = 0.0f, a3 = 0.0f;
#pragma unroll
    for (int i = 0; i < 32; i++) {
        float w0 = __shfl_sync(0xffffffffu, wv.x, i);
        float w1 = __shfl_sync(0xffffffffu, wv.y, i);
        float w2 = __shfl_sync(0xffffffffu, wv.z, i);
        float w3 = __shfl_sync(0xffffffffu, wv.w, i);
        int d = 4 * i;
        a0 += w0 * hT[(d + 0) * Bsz + lane];
        a1 += w1 * hT[(d + 1) * Bsz + lane];
        a2 += w2 * hT[(d + 2) * Bsz + lane];
        a3 += w3 * hT[(d + 3) * Bsz + lane];
    }
    float l = ((a0 + a1) + (a2 + a3) + lin_b[r]) * TAU1;
    g_wT[t][r * Bsz + lane] = expf(l);
}

// norm for state j (j>=1) = 1/max(g_sums[j-1][b], 1e-7); state 0 norm = 1
__device__ __forceinline__ float4 attn_vec(int t, int j, int q) {
    float4 e = reinterpret_cast<const float4*>(g_eatt)[(t * 4 + j) * 8 + q];
    if (j >= 1) {
        float4 s = reinterpret_cast<const float4*>(g_sums)[(j - 1) * 8 + q];
        e.x *= 1.0f / fmaxf(s.x, 1e-7f);
        e.y *= 1.0f / fmaxf(s.y, 1e-7f);
        e.z *= 1.0f / fmaxf(s.z, 1e-7f);
        e.w *= 1.0f / fmaxf(s.w, 1e-7f);
    }
    return e;
}

// ---------------- combine states -> g_inp + nz flags (t = 1 or 2) ----------
__global__ void k_inp(const int* __restrict__ input_x, int t) {
    int u = blockIdx.x * blockDim.x + threadIdx.x;
    int q = u & 7;
    float4 a0 = attn_vec(t, 0, q);
    float4 a1 = attn_vec(t, 1, q);
    float4 a2 = (t >= 2) ? attn_vec(t, 2, q) : make_float4(0, 0, 0, 0);
    int4 xi = reinterpret_cast<const int4*>(input_x)[q];
    const float4* __restrict__ s1 = reinterpret_cast<const float4*>(g_states[1]);
    const float4* __restrict__ s2 = reinterpret_cast<const float4*>(g_states[2]);
    int e = u >> 3;
    float4 v = make_float4(xi.x == e ? a0.x : 0.0f, xi.y == e ? a0.y : 0.0f,
                           xi.z == e ? a0.z : 0.0f, xi.w == e ? a0.w : 0.0f);
    {
        float4 s = s1[u];
        v.x += a1.x * s.x; v.y += a1.y * s.y; v.z += a1.z * s.z; v.w += a1.w * s.w;
    }
    if (t >= 2) {
        float4 s = s2[u];
        v.x += a2.x * s.x; v.y += a2.y * s.y; v.z += a2.z * s.z; v.w += a2.w * s.w;
    }
    reinterpret_cast<float4*>(g_inp)[u] = v;
    int lane = threadIdx.x & 31;
    bool nzv = (v.x != 0.0f) | (v.y != 0.0f) | (v.z != 0.0f) | (v.w != 0.0f);
    unsigned m = __ballot_sync(0xffffffffu, nzv);
    if ((lane & 7) == 0) g_nz[e] = ((m >> ((lane >> 3) * 8)) & 0xffu) ? 1 : 0;
}

// ---------------- propagate: sparse-aware, fused batch sums ----------------
__global__ void k_prop(const int* __restrict__ heads, const int* __restrict__ tails,
                       const int* __restrict__ rels, int t, int nE) {
    const float4* __restrict__ x4 = reinterpret_cast<const float4*>(g_inp);
    float4* s4 = reinterpret_cast<float4*>(g_states[t + 1]);
    const float4* __restrict__ w4 = reinterpret_cast<const float4*>(g_wT[t]);
    int lane = threadIdx.x & 31;
    int q = lane & 7;
    int sub = lane >> 3;
    int warpId = (blockIdx.x * blockDim.x + threadIdx.x) >> 5;
    int nWarp = (gridDim.x * blockDim.x) >> 5;
    float4 acc = make_float4(0.0f, 0.0f, 0.0f, 0.0f);
    for (int e = warpId * 4 + sub; e < nE; e += nWarp * 4) {
        int h = heads[e], tl = tails[e];
        bool fh = g_nz[h] != 0, ft = g_nz[tl] != 0;
        if (fh | ft) {
            int r = rels[e];
            if (fh) {
                float4 xh = x4[h * 8 + q];
                if (xh.x != 0.0f || xh.y != 0.0f || xh.z != 0.0f || xh.w != 0.0f) {
                    float4 w1 = w4[r * 8 + q];
                    float4 m1 = make_float4(xh.x * w1.x, xh.y * w1.y,
                                            xh.z * w1.z, xh.w * w1.w);
                    red_add_v4(&s4[tl * 8 + q], m1);
                    acc.x += m1.x; acc.y += m1.y; acc.z += m1.z; acc.w += m1.w;
                }
            }
            if (ft) {
                float4 xt = x4[tl * 8 + q];
                if (xt.x != 0.0f || xt.y != 0.0f || xt.z != 0.0f || xt.w != 0.0f) {
                    float4 w2 = w4[(r + RSIZEc) * 8 + q];
                    float4 m2 = make_float4(xt.x * w2.x, xt.y * w2.y,
                                            xt.z * w2.z, xt.w * w2.w);
                    red_add_v4(&s4[h * 8 + q], m2);
                    acc.x += m2.x; acc.y += m2.y; acc.z += m2.z; acc.w += m2.w;
                }
            }
        }
    }
    acc.x += __shfl_xor_sync(0xffffffffu, acc.x, 8);
    acc.y += __shfl_xor_sync(0xffffffffu, acc.y, 8);
    acc.z += __shfl_xor_sync(0xffffffffu, acc.z, 8);
    acc.w += __shfl_xor_sync(0xffffffffu, acc.w, 8);
    acc.x += __shfl_xor_sync(0xffffffffu, acc.x, 16);
    acc.y += __shfl_xor_sync(0xffffffffu, acc.y, 16);
    acc.z += __shfl_xor_sync(0xffffffffu, acc.z, 16);
    acc.w += __shfl_xor_sync(0xffffffffu, acc.w, 16);
    __shared__ float sblk[Bsz];
    if (threadIdx.x < Bsz) sblk[threadIdx.x] = 0.0f;
    __syncthreads();
    if (lane < 8) {
        atomicAdd(&sblk[q * 4 + 0], acc.x);
        atomicAdd(&sblk[q * 4 + 1], acc.y);
        atomicAdd(&sblk[q * 4 + 2], acc.z);
        atomicAdd(&sblk[q * 4 + 3], acc.w);
    }
    __syncthreads();
    if (threadIdx.x < Bsz) atomicAdd(&g_sums[t][threadIdx.x], sblk[threadIdx.x]);
}

// ---------------- final combine, tiled transpose to (B, E) ------------------
__global__ void k_final(const int* __restrict__ input_x, float* __restrict__ out) {
    __shared__ float tile[32][33];
    int e0 = blockIdx.x * 32;
    int r = threadIdx.x >> 3, q = threadIdx.x & 7;
    float4 a0 = attn_vec(3, 0, q);
    float4 a1 = attn_vec(3, 1, q);
    float4 a2 = attn_vec(3, 2, q);
    float4 a3 = attn_vec(3, 3, q);
    int4 xi = reinterpret_cast<const int4*>(input_x)[q];
    const float4* __restrict__ s1 = reinterpret_cast<const float4*>(g_states[1]);
    const float4* __restrict__ s2 = reinterpret_cast<const float4*>(g_states[2]);
    const float4* __restrict__ s3 = reinterpret_cast<const float4*>(g_states[3]);
    int e = e0 + r;
    int u = e * 8 + q;
    float4 v1 = s1[u], v2 = s2[u], v3 = s3[u];
    float4 v;
    v.x = (xi.x == e ? a0.x : 0.0f) + a1.x * v1.x + a2.x * v2.x + a3.x * v3.x;
    v.y = (xi.y == e ? a0.y : 0.0f) + a1.y * v1.y + a2.y * v2.y + a3.y * v3.y;
    v.z = (xi.z == e ? a0.z : 0.0f) + a1.z * v1.z + a2.z * v2.z + a3.z * v3.z;
    v.w = (xi.w == e ? a0.w : 0.0f) + a1.w * v1.w + a2.w * v2.w + a3.w * v3.w;
    tile[r][4 * q + 0] = v.x;
    tile[r][4 * q + 1] = v.y;
    tile[r][4 * q + 2] = v.z;
    tile[r][4 * q + 3] = v.w;
    __syncthreads();
    int w = threadIdx.x >> 5, lane = threadIdx.x & 31;
#pragma unroll
    for (int bb = 0; bb < 4; bb++) {
        int b = w * 4 + bb;
        out[b * Ecnt + e0 + lane] = tile[lane][b];
    }
}

// ---------------- launch ----------------------------------------------------
extern "C" void kernel_launch(void* const* d_in, const int* in_sizes, int n_in,
                              void* d_out, int out_size) {
    const int* input_x = (const int*)d_in[0];
    const int* input_r = (const int*)d_in[1];
    const int* heads   = (const int*)d_in[2];
    const int* tails   = (const int*)d_in[3];
    const int* rels    = (const int*)d_in[4];
    const float* emb_W = (const float*)d_in[5];
    const float* W_ih  = (const float*)d_in[6];
    const float* W_hh  = (const float*)d_in[7];
    const float* b_ih  = (const float*)d_in[8];
    const float* b_hh  = (const float*)d_in[9];
    const float* lin_W = (const float*)d_in[10];
    const float* lin_b = (const float*)d_in[11];
    int nE = in_sizes[2];
    float* out = (float*)d_out;

    k_pre<<<1184, 256>>>();
    k_trans<<<128, 256>>>(W_ih, W_hh);
    k_seed<<<1, 1024>>>(input_x);
    k_lstm4<<<32, 512>>>(emb_W, input_r, b_ih, b_hh);
    k_wexp<<<300, 128>>>(lin_W, lin_b);
    k_prop<<<1184, 256>>>(heads, tails, rels, 0, nE);
    for (int t = 1; t < 3; t++) {
        k_inp<<<1250, 256>>>(input_x, t);
        k_prop<<<1184, 256>>>(heads, tails, rels, t, nE);
    }
    k_final<<<1250, 256>>>(input_x, out);
}

// round 10
// speedup vs baseline: 2.8957x; 1.0610x over previous
#include <cuda_runtime.h>
#include <math.h>

#define Ecnt 40000
#define Bsz 32
#define Hd 128
#define NRELc 400
#define RSIZEc 200
#define TAU1 10.0f

// ---------------- scratch (static device memory; no allocs) ----------------
// state 0 is virtual (one-hot from input_x); states 1..3 are materialized.
__device__ float g_states[4][Ecnt * Bsz];   // [t][e*32+b]; index 0 unused
__device__ float g_inp[Ecnt * Bsz];         // att-combined input to propagate
__device__ unsigned char g_nz[Ecnt];        // per-entity nonzero flag for g_inp
__device__ float g_rnnT[4][Hd * Bsz];       // LSTM hidden, transposed [t][d*32+b]
__device__ float g_eatt[4][4][Bsz];         // softmaxed attention [t][tp][b]
__device__ float g_WihT[Hd * 4 * Hd];       // [d][k]
__device__ float g_WhhT[Hd * 4 * Hd];       // [d][k]
__device__ float g_wT[3][NRELc * Bsz];      // UNNORMALIZED exp weights [t][r*32+b]
__device__ float g_sums[3][Bsz];            // per-prop-step message sums

__device__ __forceinline__ float sigf(float x) { return 1.0f / (1.0f + expf(-x)); }

__device__ __forceinline__ void red_add_v4(float4* p, float4 v) {
    asm volatile("red.global.add.v4.f32 [%0], {%1, %2, %3, %4};"
                 :: "l"(p), "f"(v.x), "f"(v.y), "f"(v.z), "f"(v.w)
                 : "memory");
}

// ---------------- pre: zero states/nz/sums ----------------
__global__ void k_pre() {
    int i = blockIdx.x * blockDim.x + threadIdx.x;
    int stride = gridDim.x * blockDim.x;
    const float4 z = make_float4(0.0f, 0.0f, 0.0f, 0.0f);
    float4* s4 = reinterpret_cast<float4*>(g_states[1]);   // states 1..3 contiguous
    for (int j = i; j < 3 * Ecnt * 8; j += stride) s4[j] = z;
    for (int j = i; j < Ecnt / 4; j += stride) reinterpret_cast<int*>(g_nz)[j] = 0;
    if (i < 3 * Bsz) ((float*)g_sums)[i] = 0.0f;
}

// ------ tiled transposes of W_ih / W_hh + (block 128) seed of t=0 input ----
__global__ void k_trans(const float* __restrict__ W_ih,
                        const float* __restrict__ W_hh,
                        const int* __restrict__ input_x) {
    if (blockIdx.x == 128) {
        // seed: zero the 32 one-hot lines, then set the one-hot entries
        int i = threadIdx.x;  // 256 threads
        int e = input_x[i >> 3];
        reinterpret_cast<float4*>(g_inp)[e * 8 + (i & 7)] =
            make_float4(0.0f, 0.0f, 0.0f, 0.0f);
        __syncthreads();
        if (i < Bsz) {
            int e2 = input_x[i];
            g_inp[e2 * Bsz + i] = 1.0f;
            g_nz[e2] = 1;
        }
        return;
    }
    __shared__ float tile[32][33];
    int m = blockIdx.x >> 6;           // 0: ih, 1: hh
    int bid = blockIdx.x & 63;
    int kb = (bid >> 2) * 32;
    int db = (bid & 3) * 32;
    const float* __restrict__ W = m ? W_hh : W_ih;
    float* WT = m ? g_WhhT : g_WihT;
    int tx = threadIdx.x & 31, ty0 = threadIdx.x >> 5;   // 32x8
#pragma unroll
    for (int i = 0; i < 4; i++) {
        int ty = ty0 + 8 * i;
        tile[ty][tx] = W[(kb + ty) * Hd + db + tx];
    }
    __syncthreads();
#pragma unroll
    for (int i = 0; i < 4; i++) {
        int ty = ty0 + 8 * i;
        WT[(db + ty) * (4 * Hd) + kb + tx] = tile[tx][ty];
    }
}

// ------- LSTM: ih-pre + 4 steps + attention, d-split x2, 1024 thr ----------
__global__ void __launch_bounds__(1024, 1)
k_lstm4(const float* __restrict__ emb_W, const int* __restrict__ input_r,
        const float* __restrict__ b_ih, const float* __restrict__ b_hh) {
    __shared__ float xs0[Hd];
    __shared__ float xs1[Hd];
    __shared__ float cs[Hd];
    __shared__ float hist[4][Hd];
    __shared__ float gp[2][4 * Hd];
    __shared__ float attlg[4][4];
    int b = blockIdx.x, tid = threadIdx.x;
    int k = tid & 511, half = tid >> 9;
    int d0 = half * 64;
    if (tid < Hd) {
        xs0[tid] = emb_W[input_r[b] * Hd + tid];
        cs[tid] = 0.0f;
    } else if (tid < 2 * Hd) {
        xs1[tid - Hd] = emb_W[NRELc * Hd + (tid - Hd)];
    }
    __syncthreads();
    float bias = half ? 0.0f : (b_ih[k] + b_hh[k]);
    float p0a = bias, p0b = 0.0f, p1a = bias, p1b = 0.0f;
#pragma unroll 8
    for (int i = 0; i < 64; i += 2) {
        int d = d0 + i;
        float wa = g_WihT[d * (4 * Hd) + k];
        float wb = g_WihT[(d + 1) * (4 * Hd) + k];
        p0a += xs0[d] * wa;     p0b += xs0[d + 1] * wb;
        p1a += xs1[d] * wa;     p1b += xs1[d + 1] * wb;
    }
    float pre0 = p0a + p0b, pre1 = p1a + p1b;
    // ---- t = 0: h = 0, gates = pre0 directly
    gp[half][k] = pre0;
    __syncthreads();
    if (tid < Hd) {
        float ig = gp[0][tid] + gp[1][tid];
        float fg = gp[0][Hd + tid] + gp[1][Hd + tid];
        float gg = gp[0][2 * Hd + tid] + gp[1][2 * Hd + tid];
        float og = gp[0][3 * Hd + tid] + gp[1][3 * Hd + tid];
        (void)fg;  // c_prev = 0: forget-gate term vanishes
        float c = sigf(ig) * tanhf(gg);
        float h = sigf(og) * tanhf(c);
        cs[tid] = c;
        hist[0][tid] = h;
        g_rnnT[0][tid * Bsz + b] = h;
    }
    __syncthreads();
    // ---- t = 1..3
#pragma unroll
    for (int t = 1; t < 4; t++) {
        float aa = (t < 3) ? pre0 : pre1, ab = 0.0f;
        const float* hprev = hist[t - 1];
#pragma unroll 8
        for (int i = 0; i < 64; i += 2) {
            int d = d0 + i;
            aa += hprev[d] * g_WhhT[d * (4 * Hd) + k];
            ab += hprev[d + 1] * g_WhhT[(d + 1) * (4 * Hd) + k];
        }
        gp[half][k] = aa + ab;
        __syncthreads();
        if (tid < Hd) {
            float ig = gp[0][tid] + gp[1][tid];
            float fg = gp[0][Hd + tid] + gp[1][Hd + tid];
            float gg = gp[0][2 * Hd + tid] + gp[1][2 * Hd + tid];
            float og = gp[0][3 * Hd + tid] + gp[1][3 * Hd + tid];
            float c = sigf(fg) * cs[tid] + sigf(ig) * tanhf(gg);
            float h = sigf(og) * tanhf(c);
            cs[tid] = c;
            hist[t][tid] = h;
            g_rnnT[t][tid * Bsz + b] = h;
        }
        __syncthreads();
    }
    // attention logits: warps 0..15 = (t,tp)
    int w = tid >> 5, lane = tid & 31;
    if (w < 16) {
        int t = w >> 2, tp = w & 3;
        if (tp <= t) {
            float acc = 0.0f;
#pragma unroll
            for (int i = 0; i < 4; i++) {
                int d = lane + 32 * i;
                acc += hist[t][d] * hist[tp][d];
            }
#pragma unroll
            for (int s = 16; s > 0; s >>= 1) acc += __shfl_xor_sync(0xffffffffu, acc, s);
            if (lane == 0) attlg[t][tp] = acc;
        }
    }
    __syncthreads();
    if (tid < 4) {
        int tt = tid;
        float m = -1e30f;
        for (int j = 0; j <= tt; j++) m = fmaxf(m, attlg[tt][j]);
        float s = 0.0f, e[4];
        for (int j = 0; j <= tt; j++) { e[j] = expf(attlg[tt][j] - m); s += e[j]; }
        float inv = 1.0f / s;
        for (int j = 0; j < 4; j++)
            g_eatt[tt][j][b] = (j <= tt) ? e[j] * inv : 0.0f;
    }
}

// ------ relation weights, UNNORMALIZED: w = exp(tau * (h·linW_r + b_r)) -----
__global__ void k_wexp(const float* __restrict__ lin_W, const float* __restrict__ lin_b) {
    int wid = (blockIdx.x * blockDim.x + threadIdx.x) >> 5;
    int lane = threadIdx.x & 31;
    if (wid >= 3 * NRELc) return;
    int t = wid / NRELc;
    int r = wid - t * NRELc;
    float4 wv = reinterpret_cast<const float4*>(lin_W + r * Hd)[lane];
    const float* __restrict__ hT = g_rnnT[t];
    float a0 = 0.0f, a1 = 0.0f, a2 = 0.0f, a3 = 0.0f;
#pragma unroll
    for (int i = 0; i < 32; i++) {
        float w0 = __shfl_sync(0xffffffffu, wv.x, i);
        float w1 = __shfl_sync(0xffffffffu, wv.y, i);
        float w2 = __shfl_sync(0xffffffffu, wv.z, i);
        float w3 = __shfl_sync(0xffffffffu, wv.w, i);
        int d = 4 * i;
        a0 += w0 * hT[(d + 0) * Bsz + lane];
        a1 += w1 * hT[(d + 1) * Bsz + lane];
        a2 += w2 * hT[(d + 2) * Bsz + lane];
        a3 += w3 * hT[(d + 3) * Bsz + lane];
    }
    float l = ((a0 + a1) + (a2 + a3) + lin_b[r]) * TAU1;
    g_wT[t][r * Bsz + lane] = expf(l);
}

// norm for state j (j>=1) = 1/max(g_sums[j-1][b], 1e-7); state 0 norm = 1
__device__ __forceinline__ float4 attn_vec(int t, int j, int q) {
    float4 e = reinterpret_cast<const float4*>(g_eatt)[(t * 4 + j) * 8 + q];
    if (j >= 1) {
        float4 s = reinterpret_cast<const float4*>(g_sums)[(j - 1) * 8 + q];
        e.x *= 1.0f / fmaxf(s.x, 1e-7f);
        e.y *= 1.0f / fmaxf(s.y, 1e-7f);
        e.z *= 1.0f / fmaxf(s.z, 1e-7f);
        e.w *= 1.0f / fmaxf(s.w, 1e-7f);
    }
    return e;
}

// ---------------- combine states -> g_inp + nz flags (t = 1 or 2) ----------
__global__ void k_inp(const int* __restrict__ input_x, int t) {
    int u = blockIdx.x * blockDim.x + threadIdx.x;
    int q = u & 7;
    float4 a0 = attn_vec(t, 0, q);
    float4 a1 = attn_vec(t, 1, q);
    float4 a2 = (t >= 2) ? attn_vec(t, 2, q) : make_float4(0, 0, 0, 0);
    int4 xi = reinterpret_cast<const int4*>(input_x)[q];
    const float4* __restrict__ s1 = reinterpret_cast<const float4*>(g_states[1]);
    const float4* __restrict__ s2 = reinterpret_cast<const float4*>(g_states[2]);
    int e = u >> 3;
    float4 v = make_float4(xi.x == e ? a0.x : 0.0f, xi.y == e ? a0.y : 0.0f,
                           xi.z == e ? a0.z : 0.0f, xi.w == e ? a0.w : 0.0f);
    {
        float4 s = s1[u];
        v.x += a1.x * s.x; v.y += a1.y * s.y; v.z += a1.z * s.z; v.w += a1.w * s.w;
    }
    if (t >= 2) {
        float4 s = s2[u];
        v.x += a2.x * s.x; v.y += a2.y * s.y; v.z += a2.z * s.z; v.w += a2.w * s.w;
    }
    reinterpret_cast<float4*>(g_inp)[u] = v;
    int lane = threadIdx.x & 31;
    bool nzv = (v.x != 0.0f) | (v.y != 0.0f) | (v.z != 0.0f) | (v.w != 0.0f);
    unsigned m = __ballot_sync(0xffffffffu, nzv);
    if ((lane & 7) == 0) g_nz[e] = ((m >> ((lane >> 3) * 8)) & 0xffu) ? 1 : 0;
}

// ---------------- propagate: sparse-aware, fused batch sums ----------------
__global__ void k_prop(const int* __restrict__ heads, const int* __restrict__ tails,
                       const int* __restrict__ rels, int t, int nE) {
    const float4* __restrict__ x4 = reinterpret_cast<const float4*>(g_inp);
    float4* s4 = reinterpret_cast<float4*>(g_states[t + 1]);
    const float4* __restrict__ w4 = reinterpret_cast<const float4*>(g_wT[t]);
    int lane = threadIdx.x & 31;
    int q = lane & 7;
    int sub = lane >> 3;
    int warpId = (blockIdx.x * blockDim.x + threadIdx.x) >> 5;
    int nWarp = (gridDim.x * blockDim.x) >> 5;
    float4 acc = make_float4(0.0f, 0.0f, 0.0f, 0.0f);
    for (int e = warpId * 4 + sub; e < nE; e += nWarp * 4) {
        int h = heads[e], tl = tails[e];
        bool fh = g_nz[h] != 0, ft = g_nz[tl] != 0;
        if (fh | ft) {
            int r = rels[e];
            if (fh) {
                float4 xh = x4[h * 8 + q];
                if (xh.x != 0.0f || xh.y != 0.0f || xh.z != 0.0f || xh.w != 0.0f) {
                    float4 w1 = w4[r * 8 + q];
                    float4 m1 = make_float4(xh.x * w1.x, xh.y * w1.y,
                                            xh.z * w1.z, xh.w * w1.w);
                    red_add_v4(&s4[tl * 8 + q], m1);
                    acc.x += m1.x; acc.y += m1.y; acc.z += m1.z; acc.w += m1.w;
                }
            }
            if (ft) {
                float4 xt = x4[tl * 8 + q];
                if (xt.x != 0.0f || xt.y != 0.0f || xt.z != 0.0f || xt.w != 0.0f) {
                    float4 w2 = w4[(r + RSIZEc) * 8 + q];
                    float4 m2 = make_float4(xt.x * w2.x, xt.y * w2.y,
                                            xt.z * w2.z, xt.w * w2.w);
                    red_add_v4(&s4[h * 8 + q], m2);
                    acc.x += m2.x; acc.y += m2.y; acc.z += m2.z; acc.w += m2.w;
                }
            }
        }
    }
    acc.x += __shfl_xor_sync(0xffffffffu, acc.x, 8);
    acc.y += __shfl_xor_sync(0xffffffffu, acc.y, 8);
    acc.z += __shfl_xor_sync(0xffffffffu, acc.z, 8);
    acc.w += __shfl_xor_sync(0xffffffffu, acc.w, 8);
    acc.x += __shfl_xor_sync(0xffffffffu, acc.x, 16);
    acc.y += __shfl_xor_sync(0xffffffffu, acc.y, 16);
    acc.z += __shfl_xor_sync(0xffffffffu, acc.z, 16);
    acc.w += __shfl_xor_sync(0xffffffffu, acc.w, 16);
    __shared__ float sblk[Bsz];
    if (threadIdx.x < Bsz) sblk[threadIdx.x] = 0.0f;
    __syncthreads();
    if (lane < 8) {
        atomicAdd(&sblk[q * 4 + 0], acc.x);
        atomicAdd(&sblk[q * 4 + 1], acc.y);
        atomicAdd(&sblk[q * 4 + 2], acc.z);
        atomicAdd(&sblk[q * 4 + 3], acc.w);
    }
    __syncthreads();
    if (threadIdx.x < Bsz) atomicAdd(&g_sums[t][threadIdx.x], sblk[threadIdx.x]);
}

// ---------------- final combine, tiled transpose to (B, E) ------------------
__global__ void k_final(const int* __restrict__ input_x, float* __restrict__ out) {
    __shared__ float tile[32][33];
    int e0 = blockIdx.x * 32;
    int r = threadIdx.x >> 3, q = threadIdx.x & 7;
    float4 a0 = attn_vec(3, 0, q);
    float4 a1 = attn_vec(3, 1, q);
    float4 a2 = attn_vec(3, 2, q);
    float4 a3 = attn_vec(3, 3, q);
    int4 xi = reinterpret_cast<const int4*>(input_x)[q];
    const float4* __restrict__ s1 = reinterpret_cast<const float4*>(g_states[1]);
    const float4* __restrict__ s2 = reinterpret_cast<const float4*>(g_states[2]);
    const float4* __restrict__ s3 = reinterpret_cast<const float4*>(g_states[3]);
    int e = e0 + r;
    int u = e * 8 + q;
    float4 v1 = s1[u], v2 = s2[u], v3 = s3[u];
    float4 v;
    v.x = (xi.x == e ? a0.x : 0.0f) + a1.x * v1.x + a2.x * v2.x + a3.x * v3.x;
    v.y = (xi.y == e ? a0.y : 0.0f) + a1.y * v1.y + a2.y * v2.y + a3.y * v3.y;
    v.z = (xi.z == e ? a0.z : 0.0f) + a1.z * v1.z + a2.z * v2.z + a3.z * v3.z;
    v.w = (xi.w == e ? a0.w : 0.0f) + a1.w * v1.w + a2.w * v2.w + a3.w * v3.w;
    tile[r][4 * q + 0] = v.x;
    tile[r][4 * q + 1] = v.y;
    tile[r][4 * q + 2] = v.z;
    tile[r][4 * q + 3] = v.w;
    __syncthreads();
    int w = threadIdx.x >> 5, lane = threadIdx.x & 31;
#pragma unroll
    for (int bb = 0; bb < 4; bb++) {
        int b = w * 4 + bb;
        out[b * Ecnt + e0 + lane] = tile[lane][b];
    }
}

// ---------------- launch ----------------------------------------------------
extern "C" void kernel_launch(void* const* d_in, const int* in_sizes, int n_in,
                              void* d_out, int out_size) {
    const int* input_x = (const int*)d_in[0];
    const int* input_r = (const int*)d_in[1];
    const int* heads   = (const int*)d_in[2];
    const int* tails   = (const int*)d_in[3];
    const int* rels    = (const int*)d_in[4];
    const float* emb_W = (const float*)d_in[5];
    const float* W_ih  = (const float*)d_in[6];
    const float* W_hh  = (const float*)d_in[7];
    const float* b_ih  = (const float*)d_in[8];
    const float* b_hh  = (const float*)d_in[9];
    const float* lin_W = (const float*)d_in[10];
    const float* lin_b = (const float*)d_in[11];
    int nE = in_sizes[2];
    float* out = (float*)d_out;

    k_pre<<<1184, 256>>>();
    k_trans<<<129, 256>>>(W_ih, W_hh, input_x);
    k_lstm4<<<32, 1024>>>(emb_W, input_r, b_ih, b_hh);
    k_wexp<<<300, 128>>>(lin_W, lin_b);
    k_prop<<<1184, 256>>>(heads, tails, rels, 0, nE);
    for (int t = 1; t < 3; t++) {
        k_inp<<<1250, 256>>>(input_x, t);
        k_prop<<<1184, 256>>>(heads, tails, rels, t, nE);
    }
    k_final<<<1250, 256>>>(input_x, out);
}

// round 11
// speedup vs baseline: 3.0758x; 1.0622x over previous
#include <cuda_runtime.h>
#include <math.h>

#define Ecnt 40000
#define Bsz 32
#define Hd 128
#define NRELc 400
#define RSIZEc 200
#define TAU1 10.0f

// ---------------- scratch (static device memory; no allocs) ----------------
// state 0 is virtual (one-hot from input_x); states 1..3 are materialized.
__device__ float g_states[4][Ecnt * Bsz];   // [t][e*32+b]; index 0 unused
__device__ float g_inp[Ecnt * Bsz];         // att-combined input to propagate
__device__ unsigned char g_nz[Ecnt];        // per-entity nonzero flag for g_inp
__device__ float g_rnnT[4][Hd * Bsz];       // LSTM hidden, transposed [t][d*32+b]
__device__ float g_eatt[4][4][Bsz];         // softmaxed attention [t][tp][b]
__device__ float g_WihT[Hd * 4 * Hd];       // [d][k]
__device__ float g_WhhT[Hd * 4 * Hd];       // [d][k]
__device__ float g_wT[3][NRELc * Bsz];      // UNNORMALIZED exp weights [t][r*32+b]
__device__ float g_sums[3][Bsz];            // per-prop-step message sums

__device__ __forceinline__ float sigf(float x) { return 1.0f / (1.0f + expf(-x)); }

__device__ __forceinline__ void red_add_v4(float4* p, float4 v) {
    asm volatile("red.global.add.v4.f32 [%0], {%1, %2, %3, %4};"
                 :: "l"(p), "f"(v.x), "f"(v.y), "f"(v.z), "f"(v.w)
                 : "memory");
}

// ---------------- pre: zero states/nz/sums ----------------
__global__ void k_pre() {
    int i = blockIdx.x * blockDim.x + threadIdx.x;
    int stride = gridDim.x * blockDim.x;
    const float4 z = make_float4(0.0f, 0.0f, 0.0f, 0.0f);
    float4* s4 = reinterpret_cast<float4*>(g_states[1]);   // states 1..3 contiguous
    for (int j = i; j < 3 * Ecnt * 8; j += stride) s4[j] = z;
    for (int j = i; j < Ecnt / 4; j += stride) reinterpret_cast<int*>(g_nz)[j] = 0;
    if (i < 3 * Bsz) ((float*)g_sums)[i] = 0.0f;
}

// ------ tiled transposes of W_ih / W_hh + (block 128) seed of t=0 input ----
__global__ void k_trans(const float* __restrict__ W_ih,
                        const float* __restrict__ W_hh,
                        const int* __restrict__ input_x) {
    if (blockIdx.x == 128) {
        // seed: zero the 32 one-hot lines, then set the one-hot entries
        int i = threadIdx.x;  // 256 threads
        int e = input_x[i >> 3];
        reinterpret_cast<float4*>(g_inp)[e * 8 + (i & 7)] =
            make_float4(0.0f, 0.0f, 0.0f, 0.0f);
        __syncthreads();
        if (i < Bsz) {
            int e2 = input_x[i];
            g_inp[e2 * Bsz + i] = 1.0f;
            g_nz[e2] = 1;
        }
        return;
    }
    __shared__ float tile[32][33];
    int m = blockIdx.x >> 6;           // 0: ih, 1: hh
    int bid = blockIdx.x & 63;
    int kb = (bid >> 2) * 32;
    int db = (bid & 3) * 32;
    const float* __restrict__ W = m ? W_hh : W_ih;
    float* WT = m ? g_WhhT : g_WihT;
    int tx = threadIdx.x & 31, ty0 = threadIdx.x >> 5;   // 32x8
#pragma unroll
    for (int i = 0; i < 4; i++) {
        int ty = ty0 + 8 * i;
        tile[ty][tx] = W[(kb + ty) * Hd + db + tx];
    }
    __syncthreads();
#pragma unroll
    for (int i = 0; i < 4; i++) {
        int ty = ty0 + 8 * i;
        WT[(db + ty) * (4 * Hd) + kb + tx] = tile[tx][ty];
    }
}

// ------- LSTM: ih-pre + 4 steps + attention, d-split x2, 1024 thr ----------
__global__ void __launch_bounds__(1024, 1)
k_lstm4(const float* __restrict__ emb_W, const int* __restrict__ input_r,
        const float* __restrict__ b_ih, const float* __restrict__ b_hh) {
    __shared__ float xs0[Hd];
    __shared__ float xs1[Hd];
    __shared__ float cs[Hd];
    __shared__ float hist[4][Hd];
    __shared__ float gp[2][4 * Hd];
    __shared__ float attlg[4][4];
    int b = blockIdx.x, tid = threadIdx.x;
    int k = tid & 511, half = tid >> 9;
    int d0 = half * 64;
    if (tid < Hd) {
        xs0[tid] = emb_W[input_r[b] * Hd + tid];
        cs[tid] = 0.0f;
    } else if (tid < 2 * Hd) {
        xs1[tid - Hd] = emb_W[NRELc * Hd + (tid - Hd)];
    }
    __syncthreads();
    float bias = half ? 0.0f : (b_ih[k] + b_hh[k]);
    float p0a = bias, p0b = 0.0f, p1a = bias, p1b = 0.0f;
#pragma unroll 8
    for (int i = 0; i < 64; i += 2) {
        int d = d0 + i;
        float wa = g_WihT[d * (4 * Hd) + k];
        float wb = g_WihT[(d + 1) * (4 * Hd) + k];
        p0a += xs0[d] * wa;     p0b += xs0[d + 1] * wb;
        p1a += xs1[d] * wa;     p1b += xs1[d + 1] * wb;
    }
    float pre0 = p0a + p0b, pre1 = p1a + p1b;
    // ---- t = 0: h = 0, gates = pre0 directly
    gp[half][k] = pre0;
    __syncthreads();
    if (tid < Hd) {
        float ig = gp[0][tid] + gp[1][tid];
        float gg = gp[0][2 * Hd + tid] + gp[1][2 * Hd + tid];
        float og = gp[0][3 * Hd + tid] + gp[1][3 * Hd + tid];
        float c = sigf(ig) * tanhf(gg);   // c_prev = 0: forget term vanishes
        float h = sigf(og) * tanhf(c);
        cs[tid] = c;
        hist[0][tid] = h;
        g_rnnT[0][tid * Bsz + b] = h;
    }
    __syncthreads();
    // ---- t = 1..3
#pragma unroll
    for (int t = 1; t < 4; t++) {
        float aa = (t < 3) ? pre0 : pre1, ab = 0.0f;
        const float* hprev = hist[t - 1];
#pragma unroll 8
        for (int i = 0; i < 64; i += 2) {
            int d = d0 + i;
            aa += hprev[d] * g_WhhT[d * (4 * Hd) + k];
            ab += hprev[d + 1] * g_WhhT[(d + 1) * (4 * Hd) + k];
        }
        gp[half][k] = aa + ab;
        __syncthreads();
        if (tid < Hd) {
            float ig = gp[0][tid] + gp[1][tid];
            float fg = gp[0][Hd + tid] + gp[1][Hd + tid];
            float gg = gp[0][2 * Hd + tid] + gp[1][2 * Hd + tid];
            float og = gp[0][3 * Hd + tid] + gp[1][3 * Hd + tid];
            float c = sigf(fg) * cs[tid] + sigf(ig) * tanhf(gg);
            float h = sigf(og) * tanhf(c);
            cs[tid] = c;
            hist[t][tid] = h;
            g_rnnT[t][tid * Bsz + b] = h;
        }
        __syncthreads();
    }
    // attention logits: warps 0..15 = (t,tp)
    int w = tid >> 5, lane = tid & 31;
    if (w < 16) {
        int t = w >> 2, tp = w & 3;
        if (tp <= t) {
            float acc = 0.0f;
#pragma unroll
            for (int i = 0; i < 4; i++) {
                int d = lane + 32 * i;
                acc += hist[t][d] * hist[tp][d];
            }
#pragma unroll
            for (int s = 16; s > 0; s >>= 1) acc += __shfl_xor_sync(0xffffffffu, acc, s);
            if (lane == 0) attlg[t][tp] = acc;
        }
    }
    __syncthreads();
    if (tid < 4) {
        int tt = tid;
        float m = -1e30f;
        for (int j = 0; j <= tt; j++) m = fmaxf(m, attlg[tt][j]);
        float s = 0.0f, e[4];
        for (int j = 0; j <= tt; j++) { e[j] = expf(attlg[tt][j] - m); s += e[j]; }
        float inv = 1.0f / s;
        for (int j = 0; j < 4; j++)
            g_eatt[tt][j][b] = (j <= tt) ? e[j] * inv : 0.0f;
    }
}

// ------ relation weights, UNNORMALIZED: w = exp(tau * (h·linW_r + b_r)) -----
// smem-staged: block = (t, 8 r's). hT[t] (16KB) + 8 lin_W rows (4KB) staged
// once; each warp computes one r entirely from shared memory.
__global__ void k_wexp(const float* __restrict__ lin_W, const float* __restrict__ lin_b) {
    __shared__ float hs[Hd * Bsz];   // [d][b], 16 KB
    __shared__ float ws[8][Hd];      // 8 weight rows, 4 KB
    __shared__ float wb[8];
    int t = blockIdx.x / 50;
    int rbase = (blockIdx.x % 50) * 8;
    int tid = threadIdx.x;  // 256
    {
        const float4* src = reinterpret_cast<const float4*>(g_rnnT[t]);
        float4* dst = reinterpret_cast<float4*>(hs);
#pragma unroll
        for (int i = 0; i < 4; i++) dst[tid + 256 * i] = src[tid + 256 * i];
        const float4* wsrc = reinterpret_cast<const float4*>(lin_W + rbase * Hd);
        reinterpret_cast<float4*>(ws)[tid] = wsrc[tid];
        if (tid < 8) wb[tid] = lin_b[rbase + tid];
    }
    __syncthreads();
    int w = tid >> 5, lane = tid & 31;
    const float* wr = ws[w];
    float a0 = 0.0f, a1 = 0.0f, a2 = 0.0f, a3 = 0.0f;
#pragma unroll
    for (int d = 0; d < Hd; d += 4) {
        a0 += wr[d + 0] * hs[(d + 0) * Bsz + lane];
        a1 += wr[d + 1] * hs[(d + 1) * Bsz + lane];
        a2 += wr[d + 2] * hs[(d + 2) * Bsz + lane];
        a3 += wr[d + 3] * hs[(d + 3) * Bsz + lane];
    }
    float l = ((a0 + a1) + (a2 + a3) + wb[w]) * TAU1;
    g_wT[t][(rbase + w) * Bsz + lane] = expf(l);
}

// norm for state j (j>=1) = 1/max(g_sums[j-1][b], 1e-7); state 0 norm = 1
__device__ __forceinline__ float4 attn_vec(int t, int j, int q) {
    float4 e = reinterpret_cast<const float4*>(g_eatt)[(t * 4 + j) * 8 + q];
    if (j >= 1) {
        float4 s = reinterpret_cast<const float4*>(g_sums)[(j - 1) * 8 + q];
        e.x *= 1.0f / fmaxf(s.x, 1e-7f);
        e.y *= 1.0f / fmaxf(s.y, 1e-7f);
        e.z *= 1.0f / fmaxf(s.z, 1e-7f);
        e.w *= 1.0f / fmaxf(s.w, 1e-7f);
    }
    return e;
}

// ---------------- combine states -> g_inp + nz flags (t = 1 or 2) ----------
__global__ void k_inp(const int* __restrict__ input_x, int t) {
    int u = blockIdx.x * blockDim.x + threadIdx.x;
    int q = u & 7;
    float4 a0 = attn_vec(t, 0, q);
    float4 a1 = attn_vec(t, 1, q);
    float4 a2 = (t >= 2) ? attn_vec(t, 2, q) : make_float4(0, 0, 0, 0);
    int4 xi = reinterpret_cast<const int4*>(input_x)[q];
    const float4* __restrict__ s1 = reinterpret_cast<const float4*>(g_states[1]);
    const float4* __restrict__ s2 = reinterpret_cast<const float4*>(g_states[2]);
    int e = u >> 3;
    float4 v = make_float4(xi.x == e ? a0.x : 0.0f, xi.y == e ? a0.y : 0.0f,
                           xi.z == e ? a0.z : 0.0f, xi.w == e ? a0.w : 0.0f);
    {
        float4 s = s1[u];
        v.x += a1.x * s.x; v.y += a1.y * s.y; v.z += a1.z * s.z; v.w += a1.w * s.w;
    }
    if (t >= 2) {
        float4 s = s2[u];
        v.x += a2.x * s.x; v.y += a2.y * s.y; v.z += a2.z * s.z; v.w += a2.w * s.w;
    }
    reinterpret_cast<float4*>(g_inp)[u] = v;
    int lane = threadIdx.x & 31;
    bool nzv = (v.x != 0.0f) | (v.y != 0.0f) | (v.z != 0.0f) | (v.w != 0.0f);
    unsigned m = __ballot_sync(0xffffffffu, nzv);
    if ((lane & 7) == 0) g_nz[e] = ((m >> ((lane >> 3) * 8)) & 0xffu) ? 1 : 0;
}

// ---------------- propagate: sparse-aware, fused batch sums ----------------
__global__ void k_prop(const int* __restrict__ heads, const int* __restrict__ tails,
                       const int* __restrict__ rels, int t, int nE) {
    const float4* __restrict__ x4 = reinterpret_cast<const float4*>(g_inp);
    float4* s4 = reinterpret_cast<float4*>(g_states[t + 1]);
    const float4* __restrict__ w4 = reinterpret_cast<const float4*>(g_wT[t]);
    int lane = threadIdx.x & 31;
    int q = lane & 7;
    int sub = lane >> 3;
    int warpId = (blockIdx.x * blockDim.x + threadIdx.x) >> 5;
    int nWarp = (gridDim.x * blockDim.x) >> 5;
    float4 acc = make_float4(0.0f, 0.0f, 0.0f, 0.0f);
    for (int e = warpId * 4 + sub; e < nE; e += nWarp * 4) {
        int h = heads[e], tl = tails[e];
        bool fh = g_nz[h] != 0, ft = g_nz[tl] != 0;
        if (fh | ft) {
            int r = rels[e];
            if (fh) {
                float4 xh = x4[h * 8 + q];
                if (xh.x != 0.0f || xh.y != 0.0f || xh.z != 0.0f || xh.w != 0.0f) {
                    float4 w1 = w4[r * 8 + q];
                    float4 m1 = make_float4(xh.x * w1.x, xh.y * w1.y,
                                            xh.z * w1.z, xh.w * w1.w);
                    red_add_v4(&s4[tl * 8 + q], m1);
                    acc.x += m1.x; acc.y += m1.y; acc.z += m1.z; acc.w += m1.w;
                }
            }
            if (ft) {
                float4 xt = x4[tl * 8 + q];
                if (xt.x != 0.0f || xt.y != 0.0f || xt.z != 0.0f || xt.w != 0.0f) {
                    float4 w2 = w4[(r + RSIZEc) * 8 + q];
                    float4 m2 = make_float4(xt.x * w2.x, xt.y * w2.y,
                                            xt.z * w2.z, xt.w * w2.w);
                    red_add_v4(&s4[h * 8 + q], m2);
                    acc.x += m2.x; acc.y += m2.y; acc.z += m2.z; acc.w += m2.w;
                }
            }
        }
    }
    acc.x += __shfl_xor_sync(0xffffffffu, acc.x, 8);
    acc.y += __shfl_xor_sync(0xffffffffu, acc.y, 8);
    acc.z += __shfl_xor_sync(0xffffffffu, acc.z, 8);
    acc.w += __shfl_xor_sync(0xffffffffu, acc.w, 8);
    acc.x += __shfl_xor_sync(0xffffffffu, acc.x, 16);
    acc.y += __shfl_xor_sync(0xffffffffu, acc.y, 16);
    acc.z += __shfl_xor_sync(0xffffffffu, acc.z, 16);
    acc.w += __shfl_xor_sync(0xffffffffu, acc.w, 16);
    __shared__ float sblk[Bsz];
    if (threadIdx.x < Bsz) sblk[threadIdx.x] = 0.0f;
    __syncthreads();
    if (lane < 8) {
        atomicAdd(&sblk[q * 4 + 0], acc.x);
        atomicAdd(&sblk[q * 4 + 1], acc.y);
        atomicAdd(&sblk[q * 4 + 2], acc.z);
        atomicAdd(&sblk[q * 4 + 3], acc.w);
    }
    __syncthreads();
    if (threadIdx.x < Bsz) atomicAdd(&g_sums[t][threadIdx.x], sblk[threadIdx.x]);
}

// ---------------- final combine, tiled transpose to (B, E) ------------------
__global__ void k_final(const int* __restrict__ input_x, float* __restrict__ out) {
    __shared__ float tile[32][33];
    int e0 = blockIdx.x * 32;
    int r = threadIdx.x >> 3, q = threadIdx.x & 7;
    float4 a0 = attn_vec(3, 0, q);
    float4 a1 = attn_vec(3, 1, q);
    float4 a2 = attn_vec(3, 2, q);
    float4 a3 = attn_vec(3, 3, q);
    int4 xi = reinterpret_cast<const int4*>(input_x)[q];
    const float4* __restrict__ s1 = reinterpret_cast<const float4*>(g_states[1]);
    const float4* __restrict__ s2 = reinterpret_cast<const float4*>(g_states[2]);
    const float4* __restrict__ s3 = reinterpret_cast<const float4*>(g_states[3]);
    int e = e0 + r;
    int u = e * 8 + q;
    float4 v1 = s1[u], v2 = s2[u], v3 = s3[u];
    float4 v;
    v.x = (xi.x == e ? a0.x : 0.0f) + a1.x * v1.x + a2.x * v2.x + a3.x * v3.x;
    v.y = (xi.y == e ? a0.y : 0.0f) + a1.y * v1.y + a2.y * v2.y + a3.y * v3.y;
    v.z = (xi.z == e ? a0.z : 0.0f) + a1.z * v1.z + a2.z * v2.z + a3.z * v3.z;
    v.w = (xi.w == e ? a0.w : 0.0f) + a1.w * v1.w + a2.w * v2.w + a3.w * v3.w;
    tile[r][4 * q + 0] = v.x;
    tile[r][4 * q + 1] = v.y;
    tile[r][4 * q + 2] = v.z;
    tile[r][4 * q + 3] = v.w;
    __syncthreads();
    int w = threadIdx.x >> 5, lane = threadIdx.x & 31;
#pragma unroll
    for (int bb = 0; bb < 4; bb++) {
        int b = w * 4 + bb;
        out[b * Ecnt + e0 + lane] = tile[lane][b];
    }
}

// ---------------- launch ----------------------------------------------------
extern "C" void kernel_launch(void* const* d_in, const int* in_sizes, int n_in,
                              void* d_out, int out_size) {
    const int* input_x = (const int*)d_in[0];
    const int* input_r = (const int*)d_in[1];
    const int* heads   = (const int*)d_in[2];
    const int* tails   = (const int*)d_in[3];
    const int* rels    = (const int*)d_in[4];
    const float* emb_W = (const float*)d_in[5];
    const float* W_ih  = (const float*)d_in[6];
    const float* W_hh  = (const float*)d_in[7];
    const float* b_ih  = (const float*)d_in[8];
    const float* b_hh  = (const float*)d_in[9];
    const float* lin_W = (const float*)d_in[10];
    const float* lin_b = (const float*)d_in[11];
    int nE = in_sizes[2];
    float* out = (float*)d_out;

    k_pre<<<1184, 256>>>();
    k_trans<<<129, 256>>>(W_ih, W_hh, input_x);
    k_lstm4<<<32, 1024>>>(emb_W, input_r, b_ih, b_hh);
    k_wexp<<<150, 256>>>(lin_W, lin_b);
    k_prop<<<1184, 256>>>(heads, tails, rels, 0, nE);
    for (int t = 1; t < 3; t++) {
        k_inp<<<1250, 256>>>(input_x, t);
        k_prop<<<1184, 256>>>(heads, tails, rels, t, nE);
    }
    k_final<<<1250, 256>>>(input_x, out);
}